// round 1
// baseline (speedup 1.0000x reference)
#include <cuda_runtime.h>
#include <cstdint>
#include <cstddef>

#define BATCH 2
#define SEQ   1024
#define SEQ2  2048
#define PQ    128
#define HIDD  1024
#define NH    16
#define DH    64

// ---------------- scratch (static device arrays; no allocation) ----------------
__device__ float g_q[BATCH * SEQ * HIDD];
__device__ float g_kc[BATCH * SEQ * HIDD];
__device__ float g_v[BATCH * SEQ * HIDD];
__device__ float g_kp[BATCH * SEQ2 * HIDD];
__device__ float g_qg[BATCH * PQ * HIDD];
__device__ float g_qscat[BATCH * SEQ * HIDD];
__device__ float g_catt[BATCH * SEQ * HIDD];
__device__ float g_qatt[BATCH * PQ * HIDD];
__device__ int   g_idx[BATCH * PQ];
__device__ int   g_segmode[1];   // 0 = bool(1B), 1 = int32, 2 = float32

// ---------------- segment_matrix dtype probe ----------------
__global__ void probe_segmat(const uint32_t* __restrict__ p) {
    if (threadIdx.x == 0 && blockIdx.x == 0) {
        int mode = 1;  // default int32 (all dwords in {0,1})
        for (int i = 0; i < 4096; i++) {
            uint32_t w = p[i];
            if (w == 0x3F800000u) { mode = 2; break; }   // float 1.0
            if (w > 1u)           { mode = 0; break; }   // packed bools e.g. 0x00010100
        }
        g_segmode[0] = mode;
    }
}

__device__ __forceinline__ bool seg_at(const void* p, size_t i, int mode) {
    if (mode == 0) return ((const uint8_t*)p)[i] != 0;
    if (mode == 1) return ((const int*)p)[i] != 0;
    return ((const float*)p)[i] > 0.5f;
}

// ---------------- SGEMM 128x128x8, 8x8 per thread ----------------
// All calls have M % 128 == 0, N == 1024, K == 1024: no bounds checks needed.
__global__ __launch_bounds__(256) void sgemm128(
    const float* __restrict__ A, const float* __restrict__ B,
    float* __restrict__ C, int M, int N, int K)
{
    __shared__ float As[8][128];
    __shared__ float Bs[8][128];
    const int tid  = threadIdx.x;
    const int cRow = blockIdx.y * 128;
    const int cCol = blockIdx.x * 128;
    const int tRow = (tid / 16) * 8;
    const int tCol = (tid % 16) * 8;
    const int aRow = tid >> 1;
    const int aCol = (tid & 1) * 4;
    const int bRow = tid >> 5;
    const int bCol = (tid & 31) * 4;
    const float* Ap = A + (size_t)(cRow + aRow) * K + aCol;
    const float* Bp = B + (size_t)bRow * N + cCol + bCol;

    float acc[8][8] = {};
    float rM[8], rN[8];

    for (int k0 = 0; k0 < K; k0 += 8) {
        float4 a4 = *(const float4*)(Ap + k0);
        As[aCol + 0][aRow] = a4.x;
        As[aCol + 1][aRow] = a4.y;
        As[aCol + 2][aRow] = a4.z;
        As[aCol + 3][aRow] = a4.w;
        *(float4*)&Bs[bRow][bCol] = *(const float4*)(Bp + (size_t)k0 * N);
        __syncthreads();
#pragma unroll
        for (int kk = 0; kk < 8; kk++) {
#pragma unroll
            for (int i = 0; i < 8; i++) rM[i] = As[kk][tRow + i];
#pragma unroll
            for (int j = 0; j < 8; j++) rN[j] = Bs[kk][tCol + j];
#pragma unroll
            for (int i = 0; i < 8; i++)
#pragma unroll
                for (int j = 0; j < 8; j++) acc[i][j] += rM[i] * rN[j];
        }
        __syncthreads();
    }
#pragma unroll
    for (int i = 0; i < 8; i++) {
        float* Cp = C + (size_t)(cRow + tRow + i) * N + cCol + tCol;
        *(float4*)(Cp + 0) = make_float4(acc[i][0], acc[i][1], acc[i][2], acc[i][3]);
        *(float4*)(Cp + 4) = make_float4(acc[i][4], acc[i][5], acc[i][6], acc[i][7]);
    }
}

// ---------------- utility kernels ----------------
__global__ void zero_f(float* __restrict__ p, int n) {
    int i = blockIdx.x * 256 + threadIdx.x;
    if (i < n) p[i] = 0.f;
}

// scatter-add query-stream projections into [B,S,HID] per one-hot target_mapping
__global__ void scatter_q(const float* __restrict__ tmap, const float* __restrict__ qg,
                          float* __restrict__ qscat, int* __restrict__ idx)
{
    const int b = blockIdx.y, p = blockIdx.x, t = threadIdx.x;
    __shared__ int sidx;
    const float* row = tmap + ((size_t)b * PQ + p) * SEQ;
    for (int s = t; s < SEQ; s += 128)
        if (row[s] > 0.5f) sidx = s;     // exactly one hit per row
    __syncthreads();
    const int si = sidx;
    if (t == 0) idx[b * PQ + p] = si;
    const float* src = qg + ((size_t)b * PQ + p) * HIDD;
    float* dst = qscat + ((size_t)b * SEQ + si) * HIDD;
    for (int i = t; i < HIDD; i += 128) atomicAdd(&dst[i], src[i]);
}

// ---------------- fused relative attention ----------------
// One block (128 threads) per (b, h, output-row). rel_shift is applied
// analytically: position term for (q,k) uses kp row  S + k - q.
__global__ __launch_bounds__(128) void attn_kernel(
    const float* __restrict__ Q,   // [B,S,NH,DH] (content q or scattered query q)
    const float* __restrict__ KC,  // [B,S,NH,DH]
    const float* __restrict__ V,   // [B,S,NH,DH]
    const float* __restrict__ KP,  // [B,2S,NH,DH]
    const float* __restrict__ cb, const float* __restrict__ pb,
    const float* __restrict__ sb, const float* __restrict__ seg,  // seg enc [2,NH,DH]
    const void*  __restrict__ segmat,  // [B,S,S]
    const float* __restrict__ mask,    // [B,1,S,S]
    const int*   __restrict__ qidx,    // null => content stream (qrow = blockIdx.x)
    float* __restrict__ out)           // [B,S,NH,DH] or [B,P,NH,DH]
{
    const int b = blockIdx.z, h = blockIdx.y, qo = blockIdx.x;
    const int t = threadIdx.x;
    const int qrow = qidx ? qidx[b * PQ + qo] : qo;

    __shared__ float qc[DH], qp[DH], qs[DH];
    __shared__ float sc[SEQ];
    __shared__ float red[128];
    __shared__ float s01[2];

    const int mode = g_segmode[0];

    if (t < DH) {
        float qv = Q[(((size_t)b * SEQ + qrow) * NH + h) * DH + t];
        qc[t] = qv + cb[h * DH + t];
        qp[t] = qv + pb[h * DH + t];
        qs[t] = qv + sb[h * DH + t];
    }
    __syncthreads();

    // segment scalars s0, s1 (warp 0)
    if (t < 32) {
        float a0 = qs[2*t] * seg[h * DH + 2*t]        + qs[2*t+1] * seg[h * DH + 2*t+1];
        float a1 = qs[2*t] * seg[(NH + h) * DH + 2*t] + qs[2*t+1] * seg[(NH + h) * DH + 2*t+1];
#pragma unroll
        for (int o = 16; o; o >>= 1) {
            a0 += __shfl_xor_sync(0xffffffffu, a0, o);
            a1 += __shfl_xor_sync(0xffffffffu, a1, o);
        }
        if (t == 0) { s01[0] = a0; s01[1] = a1; }
    }
    __syncthreads();

    // scores: 4 warps, each handles k = warp, warp+4, ...
    const int warp = t >> 5, lane = t & 31;
    const float c0 = qc[2*lane], c1 = qc[2*lane + 1];
    const float p0 = qp[2*lane], p1 = qp[2*lane + 1];
    const size_t rowBase = ((size_t)b * SEQ + qrow) * SEQ;

    for (int k = warp; k < SEQ; k += 4) {
        const float* kcr = KC + (((size_t)b * SEQ  + k) * NH + h) * DH + 2*lane;
        const float* kpr = KP + (((size_t)b * SEQ2 + (SEQ + k - qrow)) * NH + h) * DH + 2*lane;
        float2 c2 = *(const float2*)kcr;
        float2 p2 = *(const float2*)kpr;
        float ac = c2.x * c0 + c2.y * c1;
        float ap = p2.x * p0 + p2.y * p1;
#pragma unroll
        for (int o = 16; o; o >>= 1) {
            ac += __shfl_xor_sync(0xffffffffu, ac, o);
            ap += __shfl_xor_sync(0xffffffffu, ap, o);
        }
        if (lane == 0) {
            float sg = seg_at(segmat, rowBase + k, mode) ? s01[1] : s01[0];
            sc[k] = (ac + ap + sg) * 0.125f + mask[rowBase + k] * (-1e9f);
        }
    }
    __syncthreads();

    // softmax over sc[0..S)
    float lm = -3.4e38f;
    for (int k = t; k < SEQ; k += 128) lm = fmaxf(lm, sc[k]);
    red[t] = lm; __syncthreads();
#pragma unroll
    for (int s2 = 64; s2; s2 >>= 1) {
        if (t < s2) red[t] = fmaxf(red[t], red[t + s2]);
        __syncthreads();
    }
    const float mx = red[0];
    __syncthreads();
    float ls = 0.f;
    for (int k = t; k < SEQ; k += 128) {
        float e = __expf(sc[k] - mx);
        sc[k] = e;
        ls += e;
    }
    red[t] = ls; __syncthreads();
#pragma unroll
    for (int s2 = 64; s2; s2 >>= 1) {
        if (t < s2) red[t] += red[t + s2];
        __syncthreads();
    }
    const float invZ = 1.f / red[0];
    __syncthreads();

    // out[d] = sum_k w[k] * V[b,k,h,d]   (two k-halves, coalesced over d)
    const int d = t & 63, half = t >> 6;
    const float* vp = V + (size_t)b * SEQ * NH * DH + h * DH + d;
    float acc = 0.f;
    const int k0 = half * 512;
#pragma unroll 4
    for (int k = k0; k < k0 + 512; k++)
        acc += sc[k] * vp[(size_t)k * (NH * DH)];
    red[t] = acc; __syncthreads();
    if (t < 64) {
        size_t orow = qidx ? ((size_t)b * PQ + qo) : ((size_t)b * SEQ + qo);
        out[(orow * NH + h) * DH + t] = (red[t] + red[t + 64]) * invZ;
    }
}

// ---------------- launch ----------------
extern "C" void kernel_launch(void* const* d_in, const int* in_sizes, int n_in,
                              void* d_out, int out_size)
{
    const float* content = (const float*)d_in[0];
    const float* query   = (const float*)d_in[1];
    const float* pe      = (const float*)d_in[2];
    const void*  segmat  = d_in[3];
    const float* segenc  = (const float*)d_in[4];
    const float* segbias = (const float*)d_in[5];
    const float* cmask   = (const float*)d_in[6];
    const float* qmask   = (const float*)d_in[7];
    const float* tmap    = (const float*)d_in[8];
    const float* cbias   = (const float*)d_in[9];
    const float* pbias   = (const float*)d_in[10];
    const float* wq      = (const float*)d_in[11];
    const float* wkc     = (const float*)d_in[12];
    const float* wv      = (const float*)d_in[13];
    const float* wkp     = (const float*)d_in[14];
    const float* wo      = (const float*)d_in[15];
    float* out = (float*)d_out;

    float *q, *kc, *v, *kp, *qg, *qscat, *catt, *qatt;
    int* idx;
    cudaGetSymbolAddress((void**)&q,     g_q);
    cudaGetSymbolAddress((void**)&kc,    g_kc);
    cudaGetSymbolAddress((void**)&v,     g_v);
    cudaGetSymbolAddress((void**)&kp,    g_kp);
    cudaGetSymbolAddress((void**)&qg,    g_qg);
    cudaGetSymbolAddress((void**)&qscat, g_qscat);
    cudaGetSymbolAddress((void**)&catt,  g_catt);
    cudaGetSymbolAddress((void**)&qatt,  g_qatt);
    cudaGetSymbolAddress((void**)&idx,   g_idx);

    probe_segmat<<<1, 32>>>((const uint32_t*)segmat);
    zero_f<<<(BATCH * SEQ * HIDD + 255) / 256, 256>>>(qscat, BATCH * SEQ * HIDD);

    // projections (C = A[M,1024] * W[1024,1024])
    sgemm128<<<dim3(8, 16), 256>>>(content, wq,  q,  BATCH * SEQ, HIDD, HIDD);
    sgemm128<<<dim3(8, 16), 256>>>(content, wkc, kc, BATCH * SEQ, HIDD, HIDD);
    sgemm128<<<dim3(8, 16), 256>>>(content, wv,  v,  BATCH * SEQ, HIDD, HIDD);
    sgemm128<<<dim3(8, 32), 256>>>(pe,      wkp, kp, BATCH * SEQ2, HIDD, HIDD);
    sgemm128<<<dim3(8, 2),  256>>>(query,   wq,  qg, BATCH * PQ, HIDD, HIDD);

    scatter_q<<<dim3(PQ, BATCH), 128>>>(tmap, qg, qscat, idx);

    // content-stream attention: all S rows
    attn_kernel<<<dim3(SEQ, NH, BATCH), 128>>>(
        q, kc, v, kp, cbias, pbias, segbias, segenc, segmat, cmask, nullptr, catt);
    // query-stream attention: only the P targeted rows
    attn_kernel<<<dim3(PQ, NH, BATCH), 128>>>(
        qscat, kc, v, kp, cbias, pbias, segbias, segenc, segmat, qmask, idx, qatt);

    // output projections
    sgemm128<<<dim3(8, 16), 256>>>(catt, wo, out, BATCH * SEQ, HIDD, HIDD);
    sgemm128<<<dim3(8, 2),  256>>>(qatt, wo, out + (size_t)BATCH * SEQ * HIDD,
                                   BATCH * PQ, HIDD, HIDD);
}

// round 2
// speedup vs baseline: 1.7517x; 1.7517x over previous
#include <cuda_runtime.h>
#include <cstdint>
#include <cstddef>

#define BATCH 2
#define SEQ   1024
#define SEQ2  2048
#define PQ    128
#define HIDD  1024
#define NH    16
#define DH    64

#define TQ 16
#define TK 64
#define BAND 79          // TK + TQ - 1
#define KPW  81          // padded band width (odd -> conflict-free)

// ---------------- scratch ----------------
__device__ float g_q[BATCH * SEQ * HIDD];
__device__ float g_kc[BATCH * SEQ * HIDD];
__device__ float g_v[BATCH * SEQ * HIDD];
__device__ float g_kp[BATCH * SEQ2 * HIDD];
__device__ float g_qg[BATCH * PQ * HIDD];
__device__ float g_qscat[BATCH * SEQ * HIDD];
__device__ float g_catt[BATCH * SEQ * HIDD];
__device__ float g_qatt[BATCH * PQ * HIDD];
__device__ int   g_idx[BATCH * PQ];
__device__ int   g_segmode[1];   // 0 = bool(1B), 1 = int32, 2 = float32

// ---------------- segment_matrix dtype probe ----------------
__global__ void probe_segmat(const uint32_t* __restrict__ p) {
    if (threadIdx.x == 0 && blockIdx.x == 0) {
        int mode = 1;
        for (int i = 0; i < 4096; i++) {
            uint32_t w = p[i];
            if (w == 0x3F800000u) { mode = 2; break; }
            if (w > 1u)           { mode = 0; break; }
        }
        g_segmode[0] = mode;
    }
}

__device__ __forceinline__ bool seg_at(const void* p, size_t i, int mode) {
    if (mode == 0) return ((const uint8_t*)p)[i] != 0;
    if (mode == 1) return ((const int*)p)[i] != 0;
    return ((const float*)p)[i] > 0.5f;
}

// ---------------- SGEMM 128x64 tile, 8x4 per thread ----------------
// M % 128 == 0, N % 64 == 0, K % 8 == 0 for all call sites.
__global__ __launch_bounds__(256) void sgemm64(
    const float* __restrict__ A, const float* __restrict__ B,
    float* __restrict__ C, int M, int N, int K)
{
    __shared__ float As[8][128];
    __shared__ float Bs[8][64];
    const int tid  = threadIdx.x;
    const int cRow = blockIdx.y * 128;
    const int cCol = blockIdx.x * 64;
    const int tRow = (tid >> 4) * 8;
    const int tCol = (tid & 15) * 4;
    const int aRow = tid >> 1;
    const int aCol = (tid & 1) * 4;
    const int bRow = tid >> 5;
    const int bCol = (tid & 31) * 2;
    const float* Ap = A + (size_t)(cRow + aRow) * K + aCol;
    const float* Bp = B + (size_t)bRow * N + cCol + bCol;

    float acc[8][4] = {};

    for (int k0 = 0; k0 < K; k0 += 8) {
        float4 a4 = *(const float4*)(Ap + k0);
        As[aCol + 0][aRow] = a4.x;
        As[aCol + 1][aRow] = a4.y;
        As[aCol + 2][aRow] = a4.z;
        As[aCol + 3][aRow] = a4.w;
        *(float2*)&Bs[bRow][bCol] = *(const float2*)(Bp + (size_t)k0 * N);
        __syncthreads();
#pragma unroll
        for (int kk = 0; kk < 8; kk++) {
            float4 m0 = *(const float4*)&As[kk][tRow];
            float4 m1 = *(const float4*)&As[kk][tRow + 4];
            float4 n0 = *(const float4*)&Bs[kk][tCol];
            float rm[8] = {m0.x, m0.y, m0.z, m0.w, m1.x, m1.y, m1.z, m1.w};
            float rn[4] = {n0.x, n0.y, n0.z, n0.w};
#pragma unroll
            for (int i = 0; i < 8; i++)
#pragma unroll
                for (int j = 0; j < 4; j++) acc[i][j] += rm[i] * rn[j];
        }
        __syncthreads();
    }
#pragma unroll
    for (int i = 0; i < 8; i++) {
        *(float4*)(C + (size_t)(cRow + tRow + i) * N + cCol + tCol) =
            make_float4(acc[i][0], acc[i][1], acc[i][2], acc[i][3]);
    }
}

// ---------------- utility ----------------
__global__ void zero_f(float* __restrict__ p, int n) {
    int i = blockIdx.x * 256 + threadIdx.x;
    if (i < n) p[i] = 0.f;
}

__global__ void scatter_q(const float* __restrict__ tmap, const float* __restrict__ qg,
                          float* __restrict__ qscat, int* __restrict__ idx)
{
    const int b = blockIdx.y, p = blockIdx.x, t = threadIdx.x;
    __shared__ int sidx;
    const float* row = tmap + ((size_t)b * PQ + p) * SEQ;
    for (int s = t; s < SEQ; s += 128)
        if (row[s] > 0.5f) sidx = s;
    __syncthreads();
    const int si = sidx;
    if (t == 0) idx[b * PQ + p] = si;
    const float* src = qg + ((size_t)b * PQ + p) * HIDD;
    float* dst = qscat + ((size_t)b * SEQ + si) * HIDD;
    for (int i = t; i < HIDD; i += 128) atomicAdd(&dst[i], src[i]);
}

// ---------------- tiled content-stream attention ----------------
// One CTA per (b, h, 16 consecutive q rows). 512 threads = 16 warps; warp w
// owns q row q0+w. K tiles staged transposed in smem; rel_shift handled via a
// 79-row kp band: position(q0+w, k0+kk) uses band column j = kk + 15 - w.
// smem layout (floats):
//   qcS  [16][64]          @ 0
//   dlt  [64]              @ 1024     (position_bias - content_bias)
//   sc   [16][1024]        @ 1088
//   kcT  [64][65]          @ 17472    (reused as Vs[64][65] in AV phase)
//   kpT  [64][81]          @ 21632
#define SM_QC   0
#define SM_DLT  1024
#define SM_SC   1088
#define SM_KCT  17472
#define SM_KPT  21632
#define SM_TOTF 26816   // floats -> 107264 bytes

__global__ __launch_bounds__(512) void attn_content(
    const float* __restrict__ Q, const float* __restrict__ KC,
    const float* __restrict__ V, const float* __restrict__ KP,
    const float* __restrict__ cb, const float* __restrict__ pb,
    const float* __restrict__ sb, const float* __restrict__ seg,
    const void*  __restrict__ segmat, const float* __restrict__ mask,
    float* __restrict__ out)
{
    extern __shared__ float sm[];
    float* qcS = sm + SM_QC;
    float* dlt = sm + SM_DLT;
    float* sc  = sm + SM_SC;
    float* kcT = sm + SM_KCT;
    float* Vs  = sm + SM_KCT;   // reuse
    float* kpT = sm + SM_KPT;

    const int b = blockIdx.z, h = blockIdx.y, q0 = blockIdx.x * TQ;
    const int t = threadIdx.x, w = t >> 5, l = t & 31;
    const int mode = g_segmode[0];

    // q rows + content bias; dlt = pb - cb
    for (int i = t; i < TQ * DH; i += 512) {
        int r = i >> 6, d = i & 63;
        float qv = Q[(((size_t)b * SEQ + q0 + r) * NH + h) * DH + d];
        qcS[r * 64 + d] = qv + cb[h * DH + d];
    }
    if (t < DH) dlt[t] = pb[h * DH + t] - cb[h * DH + t];
    __syncthreads();

    // segment scalars for this warp's row (kept in registers, all lanes)
    float s0 = 0.f, s1 = 0.f;
    for (int d = l; d < DH; d += 32) {
        float qs = qcS[w * 64 + d] - cb[h * DH + d] + sb[h * DH + d];
        s0 += qs * seg[h * DH + d];
        s1 += qs * seg[(NH + h) * DH + d];
    }
#pragma unroll
    for (int o = 16; o; o >>= 1) {
        s0 += __shfl_xor_sync(0xffffffffu, s0, o);
        s1 += __shfl_xor_sync(0xffffffffu, s1, o);
    }

    const size_t mrow = ((size_t)b * SEQ + q0 + w) * SEQ;

    for (int kt = 0; kt < SEQ / TK; kt++) {
        const int k0 = kt * TK;
        __syncthreads();
        // stage KC transposed
        for (int i = t; i < TK * DH; i += 512) {
            int r = i >> 6, d = i & 63;
            kcT[d * 65 + r] = KC[(((size_t)b * SEQ + k0 + r) * NH + h) * DH + d];
        }
        // stage KP band: global row g = SEQ + k0 - q0 - 15 + j, j in [0,78]
        const int gbase = SEQ + k0 - q0 - (TQ - 1);
        for (int i = t; i < BAND * DH; i += 512) {
            int j = i >> 6, d = i & 63;
            kpT[d * KPW + j] = KP[(((size_t)b * SEQ2 + gbase + j) * NH + h) * DH + d];
        }
        __syncthreads();

        float c0 = 0.f, c1 = 0.f, p0 = 0.f, p1 = 0.f;
        const int j0 = l + (TQ - 1) - w;
        const float* qrow = qcS + w * 64;
#pragma unroll
        for (int d = 0; d < DH; d++) {
            float qc = qrow[d];
            float qp = qc + dlt[d];
            c0 += qc * kcT[d * 65 + l];
            c1 += qc * kcT[d * 65 + l + 32];
            p0 += qp * kpT[d * KPW + j0];
            p1 += qp * kpT[d * KPW + j0 + 32];
        }
        float sg0 = seg_at(segmat, mrow + k0 + l, mode) ? s1 : s0;
        float sg1 = seg_at(segmat, mrow + k0 + l + 32, mode) ? s1 : s0;
        sc[w * SEQ + k0 + l]      = (c0 + p0 + sg0) * 0.125f + mask[mrow + k0 + l] * (-1e9f);
        sc[w * SEQ + k0 + l + 32] = (c1 + p1 + sg1) * 0.125f + mask[mrow + k0 + l + 32] * (-1e9f);
    }
    __syncthreads();

    // softmax (per warp over its own row)
    float mx = -3.4e38f;
    for (int k = l; k < SEQ; k += 32) mx = fmaxf(mx, sc[w * SEQ + k]);
#pragma unroll
    for (int o = 16; o; o >>= 1) mx = fmaxf(mx, __shfl_xor_sync(0xffffffffu, mx, o));
    float sum = 0.f;
    for (int k = l; k < SEQ; k += 32) {
        float e = __expf(sc[w * SEQ + k] - mx);
        sc[w * SEQ + k] = e;
        sum += e;
    }
#pragma unroll
    for (int o = 16; o; o >>= 1) sum += __shfl_xor_sync(0xffffffffu, sum, o);
    const float invZ = 1.f / sum;

    // AV: stage V tiles, each warp accumulates its row; lane owns d=l and d=l+32
    float a0 = 0.f, a1 = 0.f;
    for (int kt = 0; kt < SEQ / TK; kt++) {
        __syncthreads();
        for (int i = t; i < TK * DH; i += 512) {
            int r = i >> 6, d = i & 63;
            Vs[r * 65 + d] = V[(((size_t)b * SEQ + kt * TK + r) * NH + h) * DH + d];
        }
        __syncthreads();
        const float* wrow = sc + w * SEQ + kt * TK;
#pragma unroll 8
        for (int kk = 0; kk < TK; kk++) {
            float wt = wrow[kk];
            a0 += wt * Vs[kk * 65 + l];
            a1 += wt * Vs[kk * 65 + l + 32];
        }
    }
    float* orow = out + (((size_t)b * SEQ + q0 + w) * NH + h) * DH;
    orow[l]      = a0 * invZ;
    orow[l + 32] = a1 * invZ;
}

// ---------------- per-row attention (query stream; P=128 rows/batch) ----------------
__global__ __launch_bounds__(128) void attn_kernel(
    const float* __restrict__ Q, const float* __restrict__ KC,
    const float* __restrict__ V, const float* __restrict__ KP,
    const float* __restrict__ cb, const float* __restrict__ pb,
    const float* __restrict__ sb, const float* __restrict__ seg,
    const void*  __restrict__ segmat, const float* __restrict__ mask,
    const int*   __restrict__ qidx, float* __restrict__ out)
{
    const int b = blockIdx.z, h = blockIdx.y, qo = blockIdx.x;
    const int t = threadIdx.x;
    const int qrow = qidx[b * PQ + qo];

    __shared__ float qc[DH], qp[DH], qs[DH];
    __shared__ float scs[SEQ];
    __shared__ float red[128];
    __shared__ float s01[2];

    const int mode = g_segmode[0];

    if (t < DH) {
        float qv = Q[(((size_t)b * SEQ + qrow) * NH + h) * DH + t];
        qc[t] = qv + cb[h * DH + t];
        qp[t] = qv + pb[h * DH + t];
        qs[t] = qv + sb[h * DH + t];
    }
    __syncthreads();

    if (t < 32) {
        float a0 = qs[2*t] * seg[h * DH + 2*t]        + qs[2*t+1] * seg[h * DH + 2*t+1];
        float a1 = qs[2*t] * seg[(NH + h) * DH + 2*t] + qs[2*t+1] * seg[(NH + h) * DH + 2*t+1];
#pragma unroll
        for (int o = 16; o; o >>= 1) {
            a0 += __shfl_xor_sync(0xffffffffu, a0, o);
            a1 += __shfl_xor_sync(0xffffffffu, a1, o);
        }
        if (t == 0) { s01[0] = a0; s01[1] = a1; }
    }
    __syncthreads();

    const int warp = t >> 5, lane = t & 31;
    const float c0 = qc[2*lane], c1 = qc[2*lane + 1];
    const float p0 = qp[2*lane], p1 = qp[2*lane + 1];
    const size_t rowBase = ((size_t)b * SEQ + qrow) * SEQ;

    for (int k = warp; k < SEQ; k += 4) {
        const float* kcr = KC + (((size_t)b * SEQ  + k) * NH + h) * DH + 2*lane;
        const float* kpr = KP + (((size_t)b * SEQ2 + (SEQ + k - qrow)) * NH + h) * DH + 2*lane;
        float2 c2 = *(const float2*)kcr;
        float2 p2 = *(const float2*)kpr;
        float ac = c2.x * c0 + c2.y * c1;
        float ap = p2.x * p0 + p2.y * p1;
#pragma unroll
        for (int o = 16; o; o >>= 1) {
            ac += __shfl_xor_sync(0xffffffffu, ac, o);
            ap += __shfl_xor_sync(0xffffffffu, ap, o);
        }
        if (lane == 0) {
            float sg = seg_at(segmat, rowBase + k, mode) ? s01[1] : s01[0];
            scs[k] = (ac + ap + sg) * 0.125f + mask[rowBase + k] * (-1e9f);
        }
    }
    __syncthreads();

    float lm = -3.4e38f;
    for (int k = t; k < SEQ; k += 128) lm = fmaxf(lm, scs[k]);
    red[t] = lm; __syncthreads();
#pragma unroll
    for (int s2 = 64; s2; s2 >>= 1) {
        if (t < s2) red[t] = fmaxf(red[t], red[t + s2]);
        __syncthreads();
    }
    const float mx = red[0];
    __syncthreads();
    float ls = 0.f;
    for (int k = t; k < SEQ; k += 128) {
        float e = __expf(scs[k] - mx);
        scs[k] = e;
        ls += e;
    }
    red[t] = ls; __syncthreads();
#pragma unroll
    for (int s2 = 64; s2; s2 >>= 1) {
        if (t < s2) red[t] += red[t + s2];
        __syncthreads();
    }
    const float invZ = 1.f / red[0];
    __syncthreads();

    const int d = t & 63, half = t >> 6;
    const float* vp = V + (size_t)b * SEQ * NH * DH + h * DH + d;
    float acc = 0.f;
    const int k0 = half * 512;
#pragma unroll 4
    for (int k = k0; k < k0 + 512; k++)
        acc += scs[k] * vp[(size_t)k * (NH * DH)];
    red[t] = acc; __syncthreads();
    if (t < 64) {
        out[(((size_t)b * PQ + qo) * NH + h) * DH + t] = (red[t] + red[t + 64]) * invZ;
    }
}

// ---------------- launch ----------------
extern "C" void kernel_launch(void* const* d_in, const int* in_sizes, int n_in,
                              void* d_out, int out_size)
{
    const float* content = (const float*)d_in[0];
    const float* query   = (const float*)d_in[1];
    const float* pe      = (const float*)d_in[2];
    const void*  segmat  = d_in[3];
    const float* segenc  = (const float*)d_in[4];
    const float* segbias = (const float*)d_in[5];
    const float* cmask   = (const float*)d_in[6];
    const float* qmask   = (const float*)d_in[7];
    const float* tmap    = (const float*)d_in[8];
    const float* cbias   = (const float*)d_in[9];
    const float* pbias   = (const float*)d_in[10];
    const float* wq      = (const float*)d_in[11];
    const float* wkc     = (const float*)d_in[12];
    const float* wv      = (const float*)d_in[13];
    const float* wkp     = (const float*)d_in[14];
    const float* wo      = (const float*)d_in[15];
    float* out = (float*)d_out;

    float *q, *kc, *v, *kp, *qg, *qscat, *catt, *qatt;
    int* idx;
    cudaGetSymbolAddress((void**)&q,     g_q);
    cudaGetSymbolAddress((void**)&kc,    g_kc);
    cudaGetSymbolAddress((void**)&v,     g_v);
    cudaGetSymbolAddress((void**)&kp,    g_kp);
    cudaGetSymbolAddress((void**)&qg,    g_qg);
    cudaGetSymbolAddress((void**)&qscat, g_qscat);
    cudaGetSymbolAddress((void**)&catt,  g_catt);
    cudaGetSymbolAddress((void**)&qatt,  g_qatt);
    cudaGetSymbolAddress((void**)&idx,   g_idx);

    static bool attr_done = false;
    if (!attr_done) {
        cudaFuncSetAttribute(attn_content, cudaFuncAttributeMaxDynamicSharedMemorySize,
                             SM_TOTF * sizeof(float));
        attr_done = true;
    }

    probe_segmat<<<1, 32>>>((const uint32_t*)segmat);
    zero_f<<<(BATCH * SEQ * HIDD + 255) / 256, 256>>>(qscat, BATCH * SEQ * HIDD);

    // projections
    sgemm64<<<dim3(16, 16), 256>>>(content, wq,  q,  BATCH * SEQ,  HIDD, HIDD);
    sgemm64<<<dim3(16, 16), 256>>>(content, wkc, kc, BATCH * SEQ,  HIDD, HIDD);
    sgemm64<<<dim3(16, 16), 256>>>(content, wv,  v,  BATCH * SEQ,  HIDD, HIDD);
    sgemm64<<<dim3(16, 32), 256>>>(pe,      wkp, kp, BATCH * SEQ2, HIDD, HIDD);
    sgemm64<<<dim3(16, 2),  256>>>(query,   wq,  qg, BATCH * PQ,   HIDD, HIDD);

    scatter_q<<<dim3(PQ, BATCH), 128>>>(tmap, qg, qscat, idx);

    // content-stream attention (tiled)
    attn_content<<<dim3(SEQ / TQ, NH, BATCH), 512, SM_TOTF * sizeof(float)>>>(
        q, kc, v, kp, cbias, pbias, segbias, segenc, segmat, cmask, catt);
    // query-stream attention (per-row)
    attn_kernel<<<dim3(PQ, NH, BATCH), 128>>>(
        qscat, kc, v, kp, cbias, pbias, segbias, segenc, segmat, qmask, idx, qatt);

    // output projections
    sgemm64<<<dim3(16, 16), 256>>>(catt, wo, out, BATCH * SEQ, HIDD, HIDD);
    sgemm64<<<dim3(16, 2),  256>>>(qatt, wo, out + (size_t)BATCH * SEQ * HIDD,
                                   BATCH * PQ, HIDD, HIDD);
}

// round 3
// speedup vs baseline: 3.3105x; 1.8899x over previous
#include <cuda_runtime.h>
#include <cstdint>
#include <cstddef>

#define BATCH 2
#define SEQ   1024
#define SEQ2  2048
#define PQ    128
#define HIDD  1024
#define NH    16
#define DH    64

// ---------------- scratch (static device arrays) ----------------
__device__ float g_q[BATCH * SEQ * HIDD];
__device__ float g_kc[BATCH * SEQ * HIDD];
__device__ float g_v[BATCH * SEQ * HIDD];
__device__ float g_kp[BATCH * SEQ2 * HIDD];
__device__ float g_qg[BATCH * PQ * HIDD];
__device__ float g_qscat[BATCH * SEQ * HIDD];
__device__ float g_qq[BATCH * PQ * HIDD];
__device__ float g_cs[(size_t)BATCH * NH * SEQ * SEQ];    // content scores / weights
__device__ float g_pp[(size_t)BATCH * NH * SEQ * SEQ2];   // position scores (full)
__device__ float g_csq[(size_t)BATCH * NH * PQ * SEQ];
__device__ float g_ppq[(size_t)BATCH * NH * PQ * SEQ2];
__device__ float g_catt[BATCH * SEQ * HIDD];
__device__ float g_qatt[BATCH * PQ * HIDD];
__device__ int   g_idx[BATCH * PQ];
__device__ int   g_segmode[1];

// ---------------- segment_matrix dtype probe ----------------
__global__ void probe_segmat(const uint32_t* __restrict__ p) {
    if (threadIdx.x == 0 && blockIdx.x == 0) {
        int mode = 1;
        for (int i = 0; i < 4096; i++) {
            uint32_t w = p[i];
            if (w == 0x3F800000u) { mode = 2; break; }
            if (w > 1u)           { mode = 0; break; }
        }
        g_segmode[0] = mode;
    }
}

__device__ __forceinline__ bool seg_at(const void* p, size_t i, int mode) {
    if (mode == 0) return ((const uint8_t*)p)[i] != 0;
    if (mode == 1) return ((const int*)p)[i] != 0;
    return ((const float*)p)[i] > 0.5f;
}

// ---------------- tf32 helpers ----------------
__device__ __forceinline__ uint32_t f2tf(float f) {
    uint32_t u;
    asm("cvt.rna.tf32.f32 %0, %1;" : "=r"(u) : "f"(f));
    return u;
}

__device__ __forceinline__ void mma_tf32(float* c, const uint32_t* a, const uint32_t* b) {
    asm volatile(
        "mma.sync.aligned.m16n8k8.row.col.f32.tf32.tf32.f32 "
        "{%0,%1,%2,%3}, {%4,%5,%6,%7}, {%8,%9}, {%0,%1,%2,%3};"
        : "+f"(c[0]), "+f"(c[1]), "+f"(c[2]), "+f"(c[3])
        : "r"(a[0]), "r"(a[1]), "r"(a[2]), "r"(a[3]), "r"(b[0]), "r"(b[1]));
}

// ---------------- unified tf32 GEMM ----------------
// C = A * B  (TB=false, B is [K,N]) or  C = A * B^T  (TB=true, B is [N,K]).
// Block tile 128x64x16, 256 threads (8 warps, each 32x32).
// Batched: z = blockIdx.z decomposed as (zo, zi) with zi = z % zInner.
// All M % 128 == 0, N % 64 == 0, K % 16 == 0 at every call site.
#define ALD 132
#define BLD 68

template<bool TB>
__global__ __launch_bounds__(256) void gemm_tf32(
    const float* __restrict__ A, const float* __restrict__ B, float* __restrict__ C,
    const float* __restrict__ abias,
    int M, int N, int K, int lda, int ldb, int ldc,
    long aOut, long aIn, long bOut, long bIn, long cOut, long cIn, int zInner)
{
    __shared__ uint32_t As[16 * ALD];
    __shared__ uint32_t Bs[16 * BLD];

    const int tid = threadIdx.x;
    const int zo = blockIdx.z / zInner, zi = blockIdx.z % zInner;
    const float* Ap = A + zo * aOut + zi * aIn;
    const float* Bp = B + zo * bOut + zi * bIn;
    float*       Cp = C + zo * cOut + zi * cIn;
    const float* biasp = abias ? abias + zi * DH : nullptr;

    const int m0 = blockIdx.y * 128;
    const int n0 = blockIdx.x * 64;

    const int wid = tid >> 5, lane = tid & 31;
    const int wm = (wid & 3) * 32, wn = (wid >> 2) * 32;
    const int lr = lane >> 2, lc = lane & 3;

    float acc[2][4][4] = {};

    for (int k0 = 0; k0 < K; k0 += 16) {
        // stage A (transposed to As[k][m]), with optional bias on the k-dim
#pragma unroll
        for (int it = 0; it < 2; it++) {
            int id = tid + it * 256;
            int r = id >> 2, c4 = (id & 3) << 2;
            float4 v = *(const float4*)(Ap + (size_t)(m0 + r) * lda + k0 + c4);
            if (biasp) {
                v.x += biasp[k0 + c4];     v.y += biasp[k0 + c4 + 1];
                v.z += biasp[k0 + c4 + 2]; v.w += biasp[k0 + c4 + 3];
            }
            uint32_t* as = As + r;
            as[(c4 + 0) * ALD] = f2tf(v.x);
            as[(c4 + 1) * ALD] = f2tf(v.y);
            as[(c4 + 2) * ALD] = f2tf(v.z);
            as[(c4 + 3) * ALD] = f2tf(v.w);
        }
        // stage B to Bs[k][n]
        if (TB) {
            int r = tid >> 2, c4 = (tid & 3) << 2;   // r: n index, c4: k
            float4 v = *(const float4*)(Bp + (size_t)(n0 + r) * ldb + k0 + c4);
            uint32_t* bs = Bs + r;
            bs[(c4 + 0) * BLD] = f2tf(v.x);
            bs[(c4 + 1) * BLD] = f2tf(v.y);
            bs[(c4 + 2) * BLD] = f2tf(v.z);
            bs[(c4 + 3) * BLD] = f2tf(v.w);
        } else {
            int r = tid >> 4, c4 = (tid & 15) << 2;  // r: k index, c4: n
            float4 v = *(const float4*)(Bp + (size_t)(k0 + r) * ldb + n0 + c4);
            uint32_t* bs = Bs + r * BLD + c4;
            bs[0] = f2tf(v.x); bs[1] = f2tf(v.y);
            bs[2] = f2tf(v.z); bs[3] = f2tf(v.w);
        }
        __syncthreads();

#pragma unroll
        for (int kk = 0; kk < 16; kk += 8) {
            uint32_t af[2][4];
#pragma unroll
            for (int im = 0; im < 2; im++) {
                int m = wm + im * 16 + lr;
                af[im][0] = As[(kk + lc) * ALD + m];
                af[im][1] = As[(kk + lc) * ALD + m + 8];
                af[im][2] = As[(kk + lc + 4) * ALD + m];
                af[im][3] = As[(kk + lc + 4) * ALD + m + 8];
            }
            uint32_t bf[4][2];
#pragma unroll
            for (int jn = 0; jn < 4; jn++) {
                int n = wn + jn * 8 + lr;
                bf[jn][0] = Bs[(kk + lc) * BLD + n];
                bf[jn][1] = Bs[(kk + lc + 4) * BLD + n];
            }
#pragma unroll
            for (int im = 0; im < 2; im++)
#pragma unroll
                for (int jn = 0; jn < 4; jn++)
                    mma_tf32(acc[im][jn], af[im], bf[jn]);
        }
        __syncthreads();
    }

#pragma unroll
    for (int im = 0; im < 2; im++) {
#pragma unroll
        for (int jn = 0; jn < 4; jn++) {
            int row = m0 + wm + im * 16 + lr;
            int col = n0 + wn + jn * 8 + 2 * lc;
            *(float2*)(Cp + (size_t)row * ldc + col) =
                make_float2(acc[im][jn][0], acc[im][jn][1]);
            *(float2*)(Cp + (size_t)(row + 8) * ldc + col) =
                make_float2(acc[im][jn][2], acc[im][jn][3]);
        }
    }
}

// ---------------- utility ----------------
__global__ void zero_f(float* __restrict__ p, int n) {
    int i = blockIdx.x * 256 + threadIdx.x;
    if (i < n) p[i] = 0.f;
}

__global__ void scatter_q(const float* __restrict__ tmap, const float* __restrict__ qg,
                          float* __restrict__ qscat, int* __restrict__ idx)
{
    const int b = blockIdx.y, p = blockIdx.x, t = threadIdx.x;
    __shared__ int sidx;
    const float* row = tmap + ((size_t)b * PQ + p) * SEQ;
    for (int s = t; s < SEQ; s += 128)
        if (row[s] > 0.5f) sidx = s;
    __syncthreads();
    const int si = sidx;
    if (t == 0) idx[b * PQ + p] = si;
    const float* src = qg + ((size_t)b * PQ + p) * HIDD;
    float* dst = qscat + ((size_t)b * SEQ + si) * HIDD;
    for (int i = t; i < HIDD; i += 128) atomicAdd(&dst[i], src[i]);
}

__global__ void gather_q(const float* __restrict__ qscat, const int* __restrict__ idx,
                         float* __restrict__ qq)
{
    const int b = blockIdx.y, p = blockIdx.x, t = threadIdx.x;
    const int si = idx[b * PQ + p];
    const float* src = qscat + ((size_t)b * SEQ + si) * HIDD;
    float* dst = qq + ((size_t)b * PQ + p) * HIDD;
    for (int i = t; i < HIDD; i += 128) dst[i] = src[i];
}

// ---------------- fused shift + segment + mask + softmax ----------------
// One block per (b, h, row). Reads the contiguous PP slice r = S - qrow + k,
// builds logits, softmax, writes normalized weights in-place over cs.
__global__ __launch_bounds__(256) void softmax_kernel(
    float* __restrict__ cs, const float* __restrict__ pp,
    const float* __restrict__ qArr, const float* __restrict__ sb,
    const float* __restrict__ seg, const void* __restrict__ segmat,
    const float* __restrict__ mask, const int* __restrict__ qidx,
    int Mrows, long qBatchStride)
{
    const int b = blockIdx.z, h = blockIdx.y, qo = blockIdx.x, t = threadIdx.x;
    const int qrow = qidx ? qidx[b * PQ + qo] : qo;
    const int z = b * NH + h;
    const int mode = g_segmode[0];

    float* csrow = cs + ((size_t)z * Mrows + qo) * SEQ;
    const float* pprow = pp + ((size_t)z * Mrows + qo) * SEQ2 + (SEQ - qrow);
    const float* mrow = mask + ((size_t)b * SEQ + qrow) * SEQ;
    const size_t segbase = ((size_t)b * SEQ + qrow) * SEQ;

    __shared__ float qsv[DH];
    __shared__ float s01[2];
    __shared__ float red[256];

    if (t < DH)
        qsv[t] = qArr[qBatchStride * b + (size_t)qo * HIDD + h * DH + t] + sb[h * DH + t];
    __syncthreads();
    if (t < 64) {
        const int which = t >> 5, l = t & 31;
        const float* sgp = seg + which * NH * DH + h * DH;
        float a = qsv[l] * sgp[l] + qsv[l + 32] * sgp[l + 32];
#pragma unroll
        for (int o = 16; o; o >>= 1) a += __shfl_xor_sync(0xffffffffu, a, o);
        if (l == 0) s01[which] = a;
    }
    __syncthreads();
    const float s0 = s01[0], s1 = s01[1];

    float lg[4];
    float mx = -3.4e38f;
#pragma unroll
    for (int j = 0; j < 4; j++) {
        int k = t + j * 256;
        float sgv = seg_at(segmat, segbase + k, mode) ? s1 : s0;
        float v = (csrow[k] + pprow[k] + sgv) * 0.125f + mrow[k] * (-1e9f);
        lg[j] = v;
        mx = fmaxf(mx, v);
    }
    red[t] = mx; __syncthreads();
#pragma unroll
    for (int s2 = 128; s2; s2 >>= 1) {
        if (t < s2) red[t] = fmaxf(red[t], red[t + s2]);
        __syncthreads();
    }
    mx = red[0]; __syncthreads();

    float sum = 0.f;
#pragma unroll
    for (int j = 0; j < 4; j++) {
        float e = __expf(lg[j] - mx);
        lg[j] = e;
        sum += e;
    }
    red[t] = sum; __syncthreads();
#pragma unroll
    for (int s2 = 128; s2; s2 >>= 1) {
        if (t < s2) red[t] += red[t + s2];
        __syncthreads();
    }
    const float invZ = 1.f / red[0];
#pragma unroll
    for (int j = 0; j < 4; j++) csrow[t + j * 256] = lg[j] * invZ;
}

// ---------------- launch ----------------
extern "C" void kernel_launch(void* const* d_in, const int* in_sizes, int n_in,
                              void* d_out, int out_size)
{
    const float* content = (const float*)d_in[0];
    const float* query   = (const float*)d_in[1];
    const float* pe      = (const float*)d_in[2];
    const void*  segmat  = d_in[3];
    const float* segenc  = (const float*)d_in[4];
    const float* segbias = (const float*)d_in[5];
    const float* cmask   = (const float*)d_in[6];
    const float* qmask   = (const float*)d_in[7];
    const float* tmap    = (const float*)d_in[8];
    const float* cbias   = (const float*)d_in[9];
    const float* pbias   = (const float*)d_in[10];
    const float* wq      = (const float*)d_in[11];
    const float* wkc     = (const float*)d_in[12];
    const float* wv      = (const float*)d_in[13];
    const float* wkp     = (const float*)d_in[14];
    const float* wo      = (const float*)d_in[15];
    float* out = (float*)d_out;

    float *q, *kc, *v, *kp, *qg, *qscat, *qq, *cs, *pp, *csq, *ppq, *catt, *qatt;
    int* idx;
    cudaGetSymbolAddress((void**)&q,     g_q);
    cudaGetSymbolAddress((void**)&kc,    g_kc);
    cudaGetSymbolAddress((void**)&v,     g_v);
    cudaGetSymbolAddress((void**)&kp,    g_kp);
    cudaGetSymbolAddress((void**)&qg,    g_qg);
    cudaGetSymbolAddress((void**)&qscat, g_qscat);
    cudaGetSymbolAddress((void**)&qq,    g_qq);
    cudaGetSymbolAddress((void**)&cs,    g_cs);
    cudaGetSymbolAddress((void**)&pp,    g_pp);
    cudaGetSymbolAddress((void**)&csq,   g_csq);
    cudaGetSymbolAddress((void**)&ppq,   g_ppq);
    cudaGetSymbolAddress((void**)&catt,  g_catt);
    cudaGetSymbolAddress((void**)&qatt,  g_qatt);
    cudaGetSymbolAddress((void**)&idx,   g_idx);

    probe_segmat<<<1, 32>>>((const uint32_t*)segmat);
    zero_f<<<(BATCH * SEQ * HIDD + 255) / 256, 256>>>(qscat, BATCH * SEQ * HIDD);

    const long SH = (long)SEQ * HIDD, S2H = (long)SEQ2 * HIDD, PH = (long)PQ * HIDD;
    const long SS = (long)SEQ * SEQ, SS2 = (long)SEQ * SEQ2;
    const long PS = (long)PQ * SEQ, PS2 = (long)PQ * SEQ2;

    // projections (NN, Z=1)
    gemm_tf32<false><<<dim3(16, 16, 1), 256>>>(content, wq,  q,  nullptr,
        2048, HIDD, HIDD, HIDD, HIDD, HIDD, 0,0,0,0,0,0, 1);
    gemm_tf32<false><<<dim3(16, 16, 1), 256>>>(content, wkc, kc, nullptr,
        2048, HIDD, HIDD, HIDD, HIDD, HIDD, 0,0,0,0,0,0, 1);
    gemm_tf32<false><<<dim3(16, 16, 1), 256>>>(content, wv,  v,  nullptr,
        2048, HIDD, HIDD, HIDD, HIDD, HIDD, 0,0,0,0,0,0, 1);
    gemm_tf32<false><<<dim3(16, 32, 1), 256>>>(pe,      wkp, kp, nullptr,
        4096, HIDD, HIDD, HIDD, HIDD, HIDD, 0,0,0,0,0,0, 1);
    gemm_tf32<false><<<dim3(16, 2, 1),  256>>>(query,   wq,  qg, nullptr,
        256,  HIDD, HIDD, HIDD, HIDD, HIDD, 0,0,0,0,0,0, 1);

    scatter_q<<<dim3(PQ, BATCH), 128>>>(tmap, qg, qscat, idx);
    gather_q<<<dim3(PQ, BATCH), 128>>>(qscat, idx, qq);

    // batched NT score GEMMs (Z = B*NH, K = 64)
    gemm_tf32<true><<<dim3(16, 8, BATCH * NH), 256>>>(q, kc, cs, cbias,
        SEQ, SEQ, DH, HIDD, HIDD, SEQ,  SH, DH, SH, DH, (long)NH * SS, SS, NH);
    gemm_tf32<true><<<dim3(32, 8, BATCH * NH), 256>>>(q, kp, pp, pbias,
        SEQ, SEQ2, DH, HIDD, HIDD, SEQ2, SH, DH, S2H, DH, (long)NH * SS2, SS2, NH);
    gemm_tf32<true><<<dim3(16, 1, BATCH * NH), 256>>>(qq, kc, csq, cbias,
        PQ, SEQ, DH, HIDD, HIDD, SEQ,  PH, DH, SH, DH, (long)NH * PS, PS, NH);
    gemm_tf32<true><<<dim3(32, 1, BATCH * NH), 256>>>(qq, kp, ppq, pbias,
        PQ, SEQ2, DH, HIDD, HIDD, SEQ2, PH, DH, S2H, DH, (long)NH * PS2, PS2, NH);

    // fused shift + segment + mask + softmax -> normalized weights
    softmax_kernel<<<dim3(SEQ, NH, BATCH), 256>>>(
        cs, pp, q, segbias, segenc, segmat, cmask, nullptr, SEQ, SH);
    softmax_kernel<<<dim3(PQ, NH, BATCH), 256>>>(
        csq, ppq, qq, segbias, segenc, segmat, qmask, idx, PQ, PH);

    // AV: batched NN (N = 64)
    gemm_tf32<false><<<dim3(1, 8, BATCH * NH), 256>>>(cs, v, catt, nullptr,
        SEQ, DH, SEQ, SEQ, HIDD, HIDD, (long)NH * SS, SS, SH, DH, SH, DH, NH);
    gemm_tf32<false><<<dim3(1, 1, BATCH * NH), 256>>>(csq, v, qatt, nullptr,
        PQ, DH, SEQ, SEQ, HIDD, HIDD, (long)NH * PS, PS, SH, DH, PH, DH, NH);

    // output projections
    gemm_tf32<false><<<dim3(16, 16, 1), 256>>>(catt, wo, out, nullptr,
        2048, HIDD, HIDD, HIDD, HIDD, HIDD, 0,0,0,0,0,0, 1);
    gemm_tf32<false><<<dim3(16, 2, 1),  256>>>(qatt, wo, out + (size_t)BATCH * SEQ * HIDD, nullptr,
        256,  HIDD, HIDD, HIDD, HIDD, HIDD, 0,0,0,0,0,0, 1);
}

// round 4
// speedup vs baseline: 4.7724x; 1.4416x over previous
#include <cuda_runtime.h>
#include <cstdint>
#include <cstddef>

#define BATCH 2
#define SEQ   1024
#define SEQ2  2048
#define PQ    128
#define HIDD  1024
#define NH    16
#define DH    64
#define H3    3072

// ---------------- scratch ----------------
__device__ float g_qkv[BATCH * SEQ * H3];      // [2048][3072] = q|kc|v
__device__ float g_wpack[HIDD * H3];           // [1024][3072]
__device__ float g_kp[BATCH * SEQ2 * HIDD];
__device__ float g_qg[BATCH * PQ * HIDD];
__device__ float g_qscat[BATCH * SEQ * HIDD];
__device__ float g_qq[BATCH * PQ * HIDD];
__device__ float g_qcb[BATCH * SEQ * HIDD];
__device__ float g_qpb[BATCH * SEQ * HIDD];
__device__ float g_qqcb[BATCH * PQ * HIDD];
__device__ float g_qqpb[BATCH * PQ * HIDD];
__device__ float g_cs[(size_t)BATCH * NH * SEQ * SEQ];
__device__ float g_pp[(size_t)BATCH * NH * SEQ * SEQ2];
__device__ float g_csq[(size_t)BATCH * NH * PQ * SEQ];
__device__ float g_ppq[(size_t)BATCH * NH * PQ * SEQ2];
__device__ float g_catt[BATCH * SEQ * HIDD];
__device__ float g_qatt[BATCH * PQ * HIDD];
__device__ int   g_idx[BATCH * PQ];
__device__ int   g_segmode[1];

// ---------------- probe ----------------
__global__ void probe_segmat(const uint32_t* __restrict__ p) {
    if (threadIdx.x == 0 && blockIdx.x == 0) {
        int mode = 1;
        for (int i = 0; i < 4096; i++) {
            uint32_t w = p[i];
            if (w == 0x3F800000u) { mode = 2; break; }
            if (w > 1u)           { mode = 0; break; }
        }
        g_segmode[0] = mode;
    }
}

__device__ __forceinline__ bool seg_at(const void* p, size_t i, int mode) {
    if (mode == 0) return ((const uint8_t*)p)[i] != 0;
    if (mode == 1) return ((const int*)p)[i] != 0;
    return ((const float*)p)[i] > 0.5f;
}

// ---------------- tf32 helpers ----------------
__device__ __forceinline__ uint32_t f2tf(float f) {
    uint32_t u;
    asm("cvt.rna.tf32.f32 %0, %1;" : "=r"(u) : "f"(f));
    return u;
}

__device__ __forceinline__ void mma_tf32(float* c, const uint32_t* a, const uint32_t* b) {
    asm volatile(
        "mma.sync.aligned.m16n8k8.row.col.f32.tf32.tf32.f32 "
        "{%0,%1,%2,%3}, {%4,%5,%6,%7}, {%8,%9}, {%0,%1,%2,%3};"
        : "+f"(c[0]), "+f"(c[1]), "+f"(c[2]), "+f"(c[3])
        : "r"(a[0]), "r"(a[1]), "r"(a[2]), "r"(a[3]), "r"(b[0]), "r"(b[1]));
}

__device__ __forceinline__ void cp16(uint32_t s, const float* g) {
    asm volatile("cp.async.ca.shared.global [%0], [%1], 16;" :: "r"(s), "l"(g));
}

// ---------------- tf32 GEMM, cp.async 2-stage pipeline ----------------
// C = A*B (TB=0, B[K,N]) or A*B^T (TB=1, B[N,K]). Tile 128x64x16, 256 thr.
// All M%128==0, N%64==0, K%16==0; lda/ldb multiples of 4.
#define AST  20     // A smem stride [m][k]
#define BSTN 72     // B smem stride (NN)  [k][n]
#define BSTT 20     // B smem stride (TB)  [n][k]

template<bool TB>
__global__ __launch_bounds__(256) void gemm_tf32(
    const float* __restrict__ A, const float* __restrict__ B, float* __restrict__ C,
    int M, int N, int K, int lda, int ldb, int ldc,
    long aOut, long aIn, long bOut, long bIn, long cOut, long cIn, int zInner)
{
    __shared__ float As[2][128 * AST];
    __shared__ float Bs[2][1280];

    const int tid = threadIdx.x;
    const int zo = blockIdx.z / zInner, zi = blockIdx.z % zInner;
    const float* Ap = A + zo * aOut + zi * aIn;
    const float* Bp = B + zo * bOut + zi * bIn;
    float*       Cp = C + zo * cOut + zi * cIn;
    const int m0 = blockIdx.y * 128, n0 = blockIdx.x * 64;

    const int wid = tid >> 5, lane = tid & 31;
    const int wm = (wid & 3) * 32, wn = (wid >> 2) * 32;
    const int lr = lane >> 2, lc = lane & 3;

    uint32_t aSm[2], bSm[2];
    aSm[0] = (uint32_t)__cvta_generic_to_shared(&As[0][0]);
    aSm[1] = (uint32_t)__cvta_generic_to_shared(&As[1][0]);
    bSm[0] = (uint32_t)__cvta_generic_to_shared(&Bs[0][0]);
    bSm[1] = (uint32_t)__cvta_generic_to_shared(&Bs[1][0]);

    const int ar = tid >> 2, ac = (tid & 3) * 4;

    auto stage = [&](int kt) {
        const int k0 = kt * 16, buf = kt & 1;
        const float* ga = Ap + (size_t)(m0 + ar) * lda + k0 + ac;
        cp16(aSm[buf] + (ar * AST + ac) * 4, ga);
        cp16(aSm[buf] + ((ar + 64) * AST + ac) * 4, ga + (size_t)64 * lda);
        if (TB) {
            cp16(bSm[buf] + (ar * BSTT + ac) * 4,
                 Bp + (size_t)(n0 + ar) * ldb + k0 + ac);
        } else {
            const int br = tid >> 4, bc = (tid & 15) * 4;
            cp16(bSm[buf] + (br * BSTN + bc) * 4,
                 Bp + (size_t)(k0 + br) * ldb + n0 + bc);
        }
    };

    float acc[2][4][4] = {};

    stage(0);
    asm volatile("cp.async.commit_group;");
    const int KT = K >> 4;

    for (int kt = 0; kt < KT; kt++) {
        if (kt + 1 < KT) {
            stage(kt + 1);
            asm volatile("cp.async.commit_group;");
            asm volatile("cp.async.wait_group 1;");
        } else {
            asm volatile("cp.async.wait_group 0;");
        }
        __syncthreads();

        const float* as = As[kt & 1];
        const float* bs = Bs[kt & 1];
#pragma unroll
        for (int kk = 0; kk < 16; kk += 8) {
            uint32_t af[2][4], bf[4][2];
#pragma unroll
            for (int im = 0; im < 2; im++) {
                const int base = (wm + im * 16 + lr) * AST + kk + lc;
                af[im][0] = f2tf(as[base]);
                af[im][1] = f2tf(as[base + 8 * AST]);
                af[im][2] = f2tf(as[base + 4]);
                af[im][3] = f2tf(as[base + 8 * AST + 4]);
            }
#pragma unroll
            for (int jn = 0; jn < 4; jn++) {
                if (TB) {
                    const int bb = (wn + jn * 8 + lr) * BSTT + kk + lc;
                    bf[jn][0] = f2tf(bs[bb]);
                    bf[jn][1] = f2tf(bs[bb + 4]);
                } else {
                    const int bb = (kk + lc) * BSTN + wn + jn * 8 + lr;
                    bf[jn][0] = f2tf(bs[bb]);
                    bf[jn][1] = f2tf(bs[bb + 4 * BSTN]);
                }
            }
#pragma unroll
            for (int im = 0; im < 2; im++)
#pragma unroll
                for (int jn = 0; jn < 4; jn++)
                    mma_tf32(acc[im][jn], af[im], bf[jn]);
        }
        __syncthreads();
    }

#pragma unroll
    for (int im = 0; im < 2; im++) {
#pragma unroll
        for (int jn = 0; jn < 4; jn++) {
            const int row = m0 + wm + im * 16 + lr;
            const int col = n0 + wn + jn * 8 + 2 * lc;
            *(float2*)(Cp + (size_t)row * ldc + col) =
                make_float2(acc[im][jn][0], acc[im][jn][1]);
            *(float2*)(Cp + (size_t)(row + 8) * ldc + col) =
                make_float2(acc[im][jn][2], acc[im][jn][3]);
        }
    }
}

// ---------------- small kernels ----------------
__global__ void zero_f(float* __restrict__ p, int n) {
    int i = blockIdx.x * 256 + threadIdx.x;
    if (i < n) p[i] = 0.f;
}

__global__ void pack_w(const float* __restrict__ wq, const float* __restrict__ wkc,
                       const float* __restrict__ wv, float* __restrict__ W)
{
    int i = blockIdx.x * 256 + threadIdx.x;      // over 1024*1024
    int r = i >> 10, c = i & 1023;
    float* dst = W + (size_t)r * H3 + c;
    dst[0]    = wq[i];
    dst[1024] = wkc[i];
    dst[2048] = wv[i];
}

__global__ void add_bias2(const float* __restrict__ src, int ld,
                          const float* __restrict__ cb, const float* __restrict__ pb,
                          float* __restrict__ ocb, float* __restrict__ opb)
{
    const int row = blockIdx.x, t = threadIdx.x;
    const float* s = src + (size_t)row * ld;
    float* o1 = ocb + (size_t)row * HIDD;
    float* o2 = opb + (size_t)row * HIDD;
    for (int i = t; i < HIDD; i += 256) {
        float v = s[i];
        o1[i] = v + cb[i];
        o2[i] = v + pb[i];
    }
}

__global__ void scatter_q(const float* __restrict__ tmap, const float* __restrict__ qg,
                          float* __restrict__ qscat, int* __restrict__ idx)
{
    const int b = blockIdx.y, p = blockIdx.x, t = threadIdx.x;
    __shared__ int sidx;
    const float* row = tmap + ((size_t)b * PQ + p) * SEQ;
    for (int s = t; s < SEQ; s += 128)
        if (row[s] > 0.5f) sidx = s;
    __syncthreads();
    const int si = sidx;
    if (t == 0) idx[b * PQ + p] = si;
    const float* src = qg + ((size_t)b * PQ + p) * HIDD;
    float* dst = qscat + ((size_t)b * SEQ + si) * HIDD;
    for (int i = t; i < HIDD; i += 128) atomicAdd(&dst[i], src[i]);
}

__global__ void gather_q(const float* __restrict__ qscat, const int* __restrict__ idx,
                         float* __restrict__ qq)
{
    const int b = blockIdx.y, p = blockIdx.x, t = threadIdx.x;
    const int si = idx[b * PQ + p];
    const float* src = qscat + ((size_t)b * SEQ + si) * HIDD;
    float* dst = qq + ((size_t)b * PQ + p) * HIDD;
    for (int i = t; i < HIDD; i += 128) dst[i] = src[i];
}

// ---------------- fused shift + segment + mask + softmax ----------------
__global__ __launch_bounds__(256) void softmax_kernel(
    float* __restrict__ cs, const float* __restrict__ pp,
    const float* __restrict__ qArr, const float* __restrict__ sb,
    const float* __restrict__ seg, const void* __restrict__ segmat,
    const float* __restrict__ mask, const int* __restrict__ qidx,
    int Mrows, long qBatchStride, int ldq)
{
    const int b = blockIdx.z, h = blockIdx.y, qo = blockIdx.x, t = threadIdx.x;
    const int qrow = qidx ? qidx[b * PQ + qo] : qo;
    const int z = b * NH + h;
    const int mode = g_segmode[0];

    float* csrow = cs + ((size_t)z * Mrows + qo) * SEQ;
    const float* pprow = pp + ((size_t)z * Mrows + qo) * SEQ2 + (SEQ - qrow);
    const float* mrow = mask + ((size_t)b * SEQ + qrow) * SEQ;
    const size_t segbase = ((size_t)b * SEQ + qrow) * SEQ;

    __shared__ float qsv[DH];
    __shared__ float s01[2];
    __shared__ float red[256];

    if (t < DH)
        qsv[t] = qArr[qBatchStride * b + (size_t)qo * ldq + h * DH + t] + sb[h * DH + t];
    __syncthreads();
    if (t < 64) {
        const int which = t >> 5, l = t & 31;
        const float* sgp = seg + which * NH * DH + h * DH;
        float a = qsv[l] * sgp[l] + qsv[l + 32] * sgp[l + 32];
#pragma unroll
        for (int o = 16; o; o >>= 1) a += __shfl_xor_sync(0xffffffffu, a, o);
        if (l == 0) s01[which] = a;
    }
    __syncthreads();
    const float s0 = s01[0], s1 = s01[1];

    float lg[4];
    float mx = -3.4e38f;
#pragma unroll
    for (int j = 0; j < 4; j++) {
        int k = t + j * 256;
        float sgv = seg_at(segmat, segbase + k, mode) ? s1 : s0;
        float v = (csrow[k] + pprow[k] + sgv) * 0.125f + mrow[k] * (-1e9f);
        lg[j] = v;
        mx = fmaxf(mx, v);
    }
    red[t] = mx; __syncthreads();
#pragma unroll
    for (int s2 = 128; s2; s2 >>= 1) {
        if (t < s2) red[t] = fmaxf(red[t], red[t + s2]);
        __syncthreads();
    }
    mx = red[0]; __syncthreads();

    float sum = 0.f;
#pragma unroll
    for (int j = 0; j < 4; j++) {
        float e = __expf(lg[j] - mx);
        lg[j] = e;
        sum += e;
    }
    red[t] = sum; __syncthreads();
#pragma unroll
    for (int s2 = 128; s2; s2 >>= 1) {
        if (t < s2) red[t] += red[t + s2];
        __syncthreads();
    }
    const float invZ = 1.f / red[0];
#pragma unroll
    for (int j = 0; j < 4; j++) csrow[t + j * 256] = lg[j] * invZ;
}

// ---------------- launch ----------------
extern "C" void kernel_launch(void* const* d_in, const int* in_sizes, int n_in,
                              void* d_out, int out_size)
{
    const float* content = (const float*)d_in[0];
    const float* query   = (const float*)d_in[1];
    const float* pe      = (const float*)d_in[2];
    const void*  segmat  = d_in[3];
    const float* segenc  = (const float*)d_in[4];
    const float* segbias = (const float*)d_in[5];
    const float* cmask   = (const float*)d_in[6];
    const float* qmask   = (const float*)d_in[7];
    const float* tmap    = (const float*)d_in[8];
    const float* cbias   = (const float*)d_in[9];
    const float* pbias   = (const float*)d_in[10];
    const float* wq      = (const float*)d_in[11];
    const float* wkc     = (const float*)d_in[12];
    const float* wv      = (const float*)d_in[13];
    const float* wkp     = (const float*)d_in[14];
    const float* wo      = (const float*)d_in[15];
    float* out = (float*)d_out;

    float *qkv, *wpack, *kp, *qg, *qscat, *qq, *qcb, *qpb, *qqcb, *qqpb;
    float *cs, *pp, *csq, *ppq, *catt, *qatt;
    int* idx;
    cudaGetSymbolAddress((void**)&qkv,   g_qkv);
    cudaGetSymbolAddress((void**)&wpack, g_wpack);
    cudaGetSymbolAddress((void**)&kp,    g_kp);
    cudaGetSymbolAddress((void**)&qg,    g_qg);
    cudaGetSymbolAddress((void**)&qscat, g_qscat);
    cudaGetSymbolAddress((void**)&qq,    g_qq);
    cudaGetSymbolAddress((void**)&qcb,   g_qcb);
    cudaGetSymbolAddress((void**)&qpb,   g_qpb);
    cudaGetSymbolAddress((void**)&qqcb,  g_qqcb);
    cudaGetSymbolAddress((void**)&qqpb,  g_qqpb);
    cudaGetSymbolAddress((void**)&cs,    g_cs);
    cudaGetSymbolAddress((void**)&pp,    g_pp);
    cudaGetSymbolAddress((void**)&csq,   g_csq);
    cudaGetSymbolAddress((void**)&ppq,   g_ppq);
    cudaGetSymbolAddress((void**)&catt,  g_catt);
    cudaGetSymbolAddress((void**)&qatt,  g_qatt);
    cudaGetSymbolAddress((void**)&idx,   g_idx);

    probe_segmat<<<1, 32>>>((const uint32_t*)segmat);
    zero_f<<<(BATCH * SEQ * HIDD + 255) / 256, 256>>>(qscat, BATCH * SEQ * HIDD);
    pack_w<<<4096, 256>>>(wq, wkc, wv, wpack);

    const long SH = (long)SEQ * HIDD, S2H = (long)SEQ2 * HIDD, PH = (long)PQ * HIDD;
    const long SH3 = (long)SEQ * H3;
    const long SS = (long)SEQ * SEQ, SS2 = (long)SEQ * SEQ2;
    const long PS = (long)PQ * SEQ, PS2 = (long)PQ * SEQ2;

    // fused QKV projection: [2048,1024] x [1024,3072]
    gemm_tf32<false><<<dim3(48, 16, 1), 256>>>(content, wpack, qkv,
        2048, H3, HIDD, HIDD, H3, H3, 0,0,0,0,0,0, 1);
    // positional keys: [4096,1024] x [1024,1024]
    gemm_tf32<false><<<dim3(16, 32, 1), 256>>>(pe, wkp, kp,
        4096, HIDD, HIDD, HIDD, HIDD, HIDD, 0,0,0,0,0,0, 1);
    // query-stream projection
    gemm_tf32<false><<<dim3(16, 2, 1), 256>>>(query, wq, qg,
        256, HIDD, HIDD, HIDD, HIDD, HIDD, 0,0,0,0,0,0, 1);

    scatter_q<<<dim3(PQ, BATCH), 128>>>(tmap, qg, qscat, idx);
    gather_q<<<dim3(PQ, BATCH), 128>>>(qscat, idx, qq);

    // bias pre-add (q -> q+cb, q+pb)
    add_bias2<<<BATCH * SEQ, 256>>>(qkv, H3, cbias, pbias, qcb, qpb);
    add_bias2<<<BATCH * PQ, 256>>>(qq, HIDD, cbias, pbias, qqcb, qqpb);

    const float* kcp = qkv + 1024;
    const float* vp  = qkv + 2048;

    // batched NT score GEMMs (Z=32, K=64)
    gemm_tf32<true><<<dim3(16, 8, BATCH * NH), 256>>>(qcb, kcp, cs,
        SEQ, SEQ, DH, HIDD, H3, SEQ,  SH, DH, SH3, DH, (long)NH * SS, SS, NH);
    gemm_tf32<true><<<dim3(32, 8, BATCH * NH), 256>>>(qpb, kp, pp,
        SEQ, SEQ2, DH, HIDD, HIDD, SEQ2, SH, DH, S2H, DH, (long)NH * SS2, SS2, NH);
    gemm_tf32<true><<<dim3(16, 1, BATCH * NH), 256>>>(qqcb, kcp, csq,
        PQ, SEQ, DH, HIDD, H3, SEQ,  PH, DH, SH3, DH, (long)NH * PS, PS, NH);
    gemm_tf32<true><<<dim3(32, 1, BATCH * NH), 256>>>(qqpb, kp, ppq,
        PQ, SEQ2, DH, HIDD, HIDD, SEQ2, PH, DH, S2H, DH, (long)NH * PS2, PS2, NH);

    // fused shift + segment + mask + softmax
    softmax_kernel<<<dim3(SEQ, NH, BATCH), 256>>>(
        cs, pp, qkv, segbias, segenc, segmat, cmask, nullptr, SEQ, SH3, H3);
    softmax_kernel<<<dim3(PQ, NH, BATCH), 256>>>(
        csq, ppq, qq, segbias, segenc, segmat, qmask, idx, PQ, PH, HIDD);

    // AV (batched NN, N=64)
    gemm_tf32<false><<<dim3(1, 8, BATCH * NH), 256>>>(cs, vp, catt,
        SEQ, DH, SEQ, SEQ, H3, HIDD, (long)NH * SS, SS, SH3, DH, SH, DH, NH);
    gemm_tf32<false><<<dim3(1, 1, BATCH * NH), 256>>>(csq, vp, qatt,
        PQ, DH, SEQ, SEQ, H3, HIDD, (long)NH * PS, PS, SH3, DH, PH, DH, NH);

    // output projections
    gemm_tf32<false><<<dim3(16, 16, 1), 256>>>(catt, wo, out,
        2048, HIDD, HIDD, HIDD, HIDD, HIDD, 0,0,0,0,0,0, 1);
    gemm_tf32<false><<<dim3(16, 2, 1), 256>>>(qatt, wo, out + (size_t)BATCH * SEQ * HIDD,
        256, HIDD, HIDD, HIDD, HIDD, HIDD, 0,0,0,0,0,0, 1);
}

// round 5
// speedup vs baseline: 5.0966x; 1.0679x over previous
#include <cuda_runtime.h>
#include <cstdint>
#include <cstddef>

#define BATCH 2
#define SEQ   1024
#define SEQ2  2048
#define PQ    128
#define HIDD  1024
#define NH    16
#define DH    64
#define H3    3072

// ---------------- scratch ----------------
__device__ float g_qkv[BATCH * SEQ * H3];      // [2048][3072] = q|kc|v
__device__ float g_wpack[HIDD * H3];
__device__ float g_kp[BATCH * SEQ2 * HIDD];
__device__ float g_qg[BATCH * PQ * HIDD];
__device__ float g_qscat[BATCH * SEQ * HIDD];
__device__ float g_qq[BATCH * PQ * HIDD];
__device__ float g_qqcb[BATCH * PQ * HIDD];
__device__ float g_qqpb[BATCH * PQ * HIDD];
__device__ float g_csq[(size_t)BATCH * NH * PQ * SEQ];
__device__ float g_ppq[(size_t)BATCH * NH * PQ * SEQ2];
__device__ float g_catt[BATCH * SEQ * HIDD];
__device__ float g_qatt[BATCH * PQ * HIDD];
__device__ int   g_idx[BATCH * PQ];
__device__ int   g_segmode[1];

// ---------------- probe ----------------
__global__ void probe_segmat(const uint32_t* __restrict__ p) {
    if (threadIdx.x == 0 && blockIdx.x == 0) {
        int mode = 1;
        for (int i = 0; i < 4096; i++) {
            uint32_t w = p[i];
            if (w == 0x3F800000u) { mode = 2; break; }
            if (w > 1u)           { mode = 0; break; }
        }
        g_segmode[0] = mode;
    }
}

__device__ __forceinline__ bool seg_at(const void* p, size_t i, int mode) {
    if (mode == 0) return ((const uint8_t*)p)[i] != 0;
    if (mode == 1) return ((const int*)p)[i] != 0;
    return ((const float*)p)[i] > 0.5f;
}

// ---------------- tf32 helpers ----------------
__device__ __forceinline__ uint32_t f2tf(float f) {
    uint32_t u;
    asm("cvt.rna.tf32.f32 %0, %1;" : "=r"(u) : "f"(f));
    return u;
}

__device__ __forceinline__ void mma_tf32(float* c, const uint32_t* a, const uint32_t* b) {
    asm volatile(
        "mma.sync.aligned.m16n8k8.row.col.f32.tf32.tf32.f32 "
        "{%0,%1,%2,%3}, {%4,%5,%6,%7}, {%8,%9}, {%0,%1,%2,%3};"
        : "+f"(c[0]), "+f"(c[1]), "+f"(c[2]), "+f"(c[3])
        : "r"(a[0]), "r"(a[1]), "r"(a[2]), "r"(a[3]), "r"(b[0]), "r"(b[1]));
}

__device__ __forceinline__ void cp16(uint32_t s, const float* g) {
    asm volatile("cp.async.ca.shared.global [%0], [%1], 16;" :: "r"(s), "l"(g));
}

// ---------------- tf32 GEMM, cp.async 2-stage (unchanged from R4) ----------------
#define AST  20
#define BSTN 72
#define BSTT 20

template<bool TB>
__global__ __launch_bounds__(256) void gemm_tf32(
    const float* __restrict__ A, const float* __restrict__ B, float* __restrict__ C,
    int M, int N, int K, int lda, int ldb, int ldc,
    long aOut, long aIn, long bOut, long bIn, long cOut, long cIn, int zInner)
{
    __shared__ float As[2][128 * AST];
    __shared__ float Bs[2][1280];

    const int tid = threadIdx.x;
    const int zo = blockIdx.z / zInner, zi = blockIdx.z % zInner;
    const float* Ap = A + zo * aOut + zi * aIn;
    const float* Bp = B + zo * bOut + zi * bIn;
    float*       Cp = C + zo * cOut + zi * cIn;
    const int m0 = blockIdx.y * 128, n0 = blockIdx.x * 64;

    const int wid = tid >> 5, lane = tid & 31;
    const int wm = (wid & 3) * 32, wn = (wid >> 2) * 32;
    const int lr = lane >> 2, lc = lane & 3;

    uint32_t aSm[2], bSm[2];
    aSm[0] = (uint32_t)__cvta_generic_to_shared(&As[0][0]);
    aSm[1] = (uint32_t)__cvta_generic_to_shared(&As[1][0]);
    bSm[0] = (uint32_t)__cvta_generic_to_shared(&Bs[0][0]);
    bSm[1] = (uint32_t)__cvta_generic_to_shared(&Bs[1][0]);

    const int ar = tid >> 2, ac = (tid & 3) * 4;

    auto stage = [&](int kt) {
        const int k0 = kt * 16, buf = kt & 1;
        const float* ga = Ap + (size_t)(m0 + ar) * lda + k0 + ac;
        cp16(aSm[buf] + (ar * AST + ac) * 4, ga);
        cp16(aSm[buf] + ((ar + 64) * AST + ac) * 4, ga + (size_t)64 * lda);
        if (TB) {
            cp16(bSm[buf] + (ar * BSTT + ac) * 4,
                 Bp + (size_t)(n0 + ar) * ldb + k0 + ac);
        } else {
            const int br = tid >> 4, bc = (tid & 15) * 4;
            cp16(bSm[buf] + (br * BSTN + bc) * 4,
                 Bp + (size_t)(k0 + br) * ldb + n0 + bc);
        }
    };

    float acc[2][4][4] = {};

    stage(0);
    asm volatile("cp.async.commit_group;");
    const int KT = K >> 4;

    for (int kt = 0; kt < KT; kt++) {
        if (kt + 1 < KT) {
            stage(kt + 1);
            asm volatile("cp.async.commit_group;");
            asm volatile("cp.async.wait_group 1;");
        } else {
            asm volatile("cp.async.wait_group 0;");
        }
        __syncthreads();

        const float* as = As[kt & 1];
        const float* bs = Bs[kt & 1];
#pragma unroll
        for (int kk = 0; kk < 16; kk += 8) {
            uint32_t af[2][4], bf[4][2];
#pragma unroll
            for (int im = 0; im < 2; im++) {
                const int base = (wm + im * 16 + lr) * AST + kk + lc;
                af[im][0] = f2tf(as[base]);
                af[im][1] = f2tf(as[base + 8 * AST]);
                af[im][2] = f2tf(as[base + 4]);
                af[im][3] = f2tf(as[base + 8 * AST + 4]);
            }
#pragma unroll
            for (int jn = 0; jn < 4; jn++) {
                if (TB) {
                    const int bb = (wn + jn * 8 + lr) * BSTT + kk + lc;
                    bf[jn][0] = f2tf(bs[bb]);
                    bf[jn][1] = f2tf(bs[bb + 4]);
                } else {
                    const int bb = (kk + lc) * BSTN + wn + jn * 8 + lr;
                    bf[jn][0] = f2tf(bs[bb]);
                    bf[jn][1] = f2tf(bs[bb + 4 * BSTN]);
                }
            }
#pragma unroll
            for (int im = 0; im < 2; im++)
#pragma unroll
                for (int jn = 0; jn < 4; jn++)
                    mma_tf32(acc[im][jn], af[im], bf[jn]);
        }
        __syncthreads();
    }

#pragma unroll
    for (int im = 0; im < 2; im++) {
#pragma unroll
        for (int jn = 0; jn < 4; jn++) {
            const int row = m0 + wm + im * 16 + lr;
            const int col = n0 + wn + jn * 8 + 2 * lc;
            *(float2*)(Cp + (size_t)row * ldc + col) =
                make_float2(acc[im][jn][0], acc[im][jn][1]);
            *(float2*)(Cp + (size_t)(row + 8) * ldc + col) =
                make_float2(acc[im][jn][2], acc[im][jn][3]);
        }
    }
}

// ---------------- flash-fused content attention ----------------
#define FST 68
#define RT  (128 * FST)

__device__ __forceinline__ void stage64(float* dst, const float* src, long rstride, int tid) {
    uint32_t s = (uint32_t)__cvta_generic_to_shared(dst);
#pragma unroll
    for (int i = 0; i < 4; i++) {
        int id = tid + i * 256;
        int j = id >> 4, d4 = (id & 15) * 4;
        cp16(s + (uint32_t)(j * FST + d4) * 4, src + (size_t)j * rstride + d4);
    }
}

__global__ __launch_bounds__(256, 1) void flash_content(
    const float* __restrict__ qkv, const float* __restrict__ kp,
    const float* __restrict__ cb, const float* __restrict__ pb,
    const float* __restrict__ sb, const float* __restrict__ seg,
    const void* __restrict__ segmat, const float* __restrict__ mask,
    float* __restrict__ out)
{
    extern __shared__ float sm[];
    float* KCs  = sm;                         // 64*FST
    float* KPs  = sm + 64 * FST;
    float* Vs   = sm + 2 * 64 * FST;
    float* Ps   = sm + 3 * 64 * FST;          // 128*FST
    float* ring = sm + 3 * 64 * FST + RT;     // 3*RT
    float* s0s  = ring + 3 * RT;
    float* s1s  = s0s + 128;

    const int b = blockIdx.z, h = blockIdx.y, q0 = blockIdx.x * 128;
    const int tid = threadIdx.x, w = tid >> 5, l = tid & 31;
    const int lr = l >> 2, lc = l & 3;
    const int qb = w * 16;
    const int mode = g_segmode[0];
    const int qt6 = q0 >> 6;

    // Q fragments (+cb, +pb) in registers, tf32
    uint32_t aC[8][4], aP[8][4];
    {
        const float* r0 = qkv + ((size_t)(b * SEQ + q0 + qb + lr)) * H3 + h * DH;
        const float* r1 = r0 + (size_t)8 * H3;
#pragma unroll
        for (int s = 0; s < 8; s++) {
            const int d0 = 8 * s + lc, d1 = d0 + 4;
            const float c0v = cb[h * DH + d0], c1v = cb[h * DH + d1];
            const float p0v = pb[h * DH + d0], p1v = pb[h * DH + d1];
            float v00 = r0[d0], v01 = r0[d1], v10 = r1[d0], v11 = r1[d1];
            aC[s][0] = f2tf(v00 + c0v); aC[s][1] = f2tf(v10 + c0v);
            aC[s][2] = f2tf(v01 + c1v); aC[s][3] = f2tf(v11 + c1v);
            aP[s][0] = f2tf(v00 + p0v); aP[s][1] = f2tf(v10 + p0v);
            aP[s][2] = f2tf(v01 + p1v); aP[s][3] = f2tf(v11 + p1v);
        }
    }
    // segment scalars per local q row
    if (tid < 128) {
        const float* qr = qkv + ((size_t)(b * SEQ + q0 + tid)) * H3 + h * DH;
        float s0 = 0.f, s1 = 0.f;
        for (int d = 0; d < DH; d++) {
            float qs = qr[d] + sb[h * DH + d];
            s0 += qs * seg[h * DH + d];
            s1 += qs * seg[NH * DH + h * DH + d];
        }
        s0s[tid] = s0; s1s[tid] = s1;
    }

    float O[8][4] = {};
    float m_a = -1e30f, m_b = -1e30f, l_a = 0.f, l_b = 0.f;

    // PP tile: (Q+pb) x KPs^T -> ring[slot] (warp-private rows)
    auto pp_tile = [&](int slot) {
#pragma unroll
        for (int jn = 0; jn < 8; jn++) {
            float c[4] = {0.f, 0.f, 0.f, 0.f};
            const float* bp = KPs + (jn * 8 + lr) * FST;
#pragma unroll
            for (int s = 0; s < 8; s++) {
                uint32_t bfr[2];
                bfr[0] = f2tf(bp[8 * s + lc]);
                bfr[1] = f2tf(bp[8 * s + lc + 4]);
                mma_tf32(c, aP[s], bfr);
            }
            float* r0 = ring + slot * RT + (qb + lr) * FST + jn * 8 + 2 * lc;
            *(float2*)r0 = make_float2(c[0], c[1]);
            *(float2*)(r0 + 8 * FST) = make_float2(c[2], c[3]);
        }
    };

    // prologue: two PP tiles (r-tiles S-q0-128, S-q0-64)
    {
        const int R0 = SEQ - q0 - 128;
        stage64(KPs, kp + ((size_t)(b * SEQ2 + R0)) * HIDD + h * DH, HIDD, tid);
        asm volatile("cp.async.commit_group;");
        asm volatile("cp.async.wait_group 0;");
        __syncthreads();
        pp_tile((14 - qt6) % 3);
        __syncthreads();
        stage64(KPs, kp + ((size_t)(b * SEQ2 + R0 + 64)) * HIDD + h * DH, HIDD, tid);
        asm volatile("cp.async.commit_group;");
        asm volatile("cp.async.wait_group 0;");
        __syncthreads();
        pp_tile((15 - qt6) % 3);
    }

    const size_t mbase_a = ((size_t)b * SEQ + q0 + qb + lr) * SEQ;
    const size_t mbase_b = mbase_a + (size_t)8 * SEQ;
    const int ra = qb + lr, rb = ra + 8;

    for (int kt = 0; kt < 16; kt++) {
        const int k0 = kt * 64;
        __syncthreads();
        stage64(KCs, qkv + ((size_t)(b * SEQ + k0)) * H3 + 1024 + h * DH, H3, tid);
        stage64(Vs,  qkv + ((size_t)(b * SEQ + k0)) * H3 + 2048 + h * DH, H3, tid);
        stage64(KPs, kp + ((size_t)(b * SEQ2 + SEQ + k0 - q0)) * HIDD + h * DH, HIDD, tid);
        asm volatile("cp.async.commit_group;");
        asm volatile("cp.async.wait_group 0;");
        __syncthreads();

        const int bT = 14 + kt - qt6;
        pp_tile((bT + 2) % 3);

        // content scores
        float cs[8][4];
#pragma unroll
        for (int jn = 0; jn < 8; jn++) {
            float c[4] = {0.f, 0.f, 0.f, 0.f};
            const float* bp = KCs + (jn * 8 + lr) * FST;
#pragma unroll
            for (int s = 0; s < 8; s++) {
                uint32_t bfr[2];
                bfr[0] = f2tf(bp[8 * s + lc]);
                bfr[1] = f2tf(bp[8 * s + lc + 4]);
                mma_tf32(c, aC[s], bfr);
            }
            cs[jn][0] = c[0]; cs[jn][1] = c[1]; cs[jn][2] = c[2]; cs[jn][3] = c[3];
        }

        const int slots[3] = {bT % 3, (bT + 1) % 3, (bT + 2) % 3};
        const float s0a = s0s[ra], s1a = s1s[ra], s0b = s0s[rb], s1b = s1s[rb];

        float mxa = -1e30f, mxb = -1e30f;
#pragma unroll
        for (int jn = 0; jn < 8; jn++) {
            const int kkp = jn * 8 + 2 * lc;
            float2 mva = *(const float2*)(mask + mbase_a + k0 + kkp);
            float2 mvb = *(const float2*)(mask + mbase_b + k0 + kkp);
            float sa0 = seg_at(segmat, mbase_a + k0 + kkp, mode)     ? s1a : s0a;
            float sa1 = seg_at(segmat, mbase_a + k0 + kkp + 1, mode) ? s1a : s0a;
            float sb0 = seg_at(segmat, mbase_b + k0 + kkp, mode)     ? s1b : s0b;
            float sb1 = seg_at(segmat, mbase_b + k0 + kkp + 1, mode) ? s1b : s0b;
            const int wa = kkp - ra + 128, wb = kkp - rb + 128;
            float ppa0 = ring[slots[wa >> 6] * RT + ra * FST + (wa & 63)];
            float ppa1 = ring[slots[(wa + 1) >> 6] * RT + ra * FST + ((wa + 1) & 63)];
            float ppb0 = ring[slots[wb >> 6] * RT + rb * FST + (wb & 63)];
            float ppb1 = ring[slots[(wb + 1) >> 6] * RT + rb * FST + ((wb + 1) & 63)];
            cs[jn][0] = (cs[jn][0] + ppa0 + sa0) * 0.125f + mva.x * (-1e9f);
            cs[jn][1] = (cs[jn][1] + ppa1 + sa1) * 0.125f + mva.y * (-1e9f);
            cs[jn][2] = (cs[jn][2] + ppb0 + sb0) * 0.125f + mvb.x * (-1e9f);
            cs[jn][3] = (cs[jn][3] + ppb1 + sb1) * 0.125f + mvb.y * (-1e9f);
            mxa = fmaxf(mxa, fmaxf(cs[jn][0], cs[jn][1]));
            mxb = fmaxf(mxb, fmaxf(cs[jn][2], cs[jn][3]));
        }
        mxa = fmaxf(mxa, __shfl_xor_sync(0xffffffffu, mxa, 1));
        mxa = fmaxf(mxa, __shfl_xor_sync(0xffffffffu, mxa, 2));
        mxb = fmaxf(mxb, __shfl_xor_sync(0xffffffffu, mxb, 1));
        mxb = fmaxf(mxb, __shfl_xor_sync(0xffffffffu, mxb, 2));

        const float mna = fmaxf(m_a, mxa), mnb = fmaxf(m_b, mxb);
        const float alA = __expf(m_a - mna), alB = __expf(m_b - mnb);
        m_a = mna; m_b = mnb;

        float sa = 0.f, sbm = 0.f;
#pragma unroll
        for (int jn = 0; jn < 8; jn++) {
            float p0 = __expf(cs[jn][0] - m_a), p1 = __expf(cs[jn][1] - m_a);
            float p2 = __expf(cs[jn][2] - m_b), p3 = __expf(cs[jn][3] - m_b);
            sa += p0 + p1; sbm += p2 + p3;
            *(float2*)(Ps + ra * FST + jn * 8 + 2 * lc) = make_float2(p0, p1);
            *(float2*)(Ps + rb * FST + jn * 8 + 2 * lc) = make_float2(p2, p3);
            O[jn][0] *= alA; O[jn][1] *= alA; O[jn][2] *= alB; O[jn][3] *= alB;
        }
        sa  += __shfl_xor_sync(0xffffffffu, sa, 1);
        sa  += __shfl_xor_sync(0xffffffffu, sa, 2);
        sbm += __shfl_xor_sync(0xffffffffu, sbm, 1);
        sbm += __shfl_xor_sync(0xffffffffu, sbm, 2);
        l_a = l_a * alA + sa;
        l_b = l_b * alB + sbm;
        __syncwarp();

        // AV
        uint32_t ap[8][4];
#pragma unroll
        for (int s = 0; s < 8; s++) {
            ap[s][0] = f2tf(Ps[ra * FST + 8 * s + lc]);
            ap[s][1] = f2tf(Ps[rb * FST + 8 * s + lc]);
            ap[s][2] = f2tf(Ps[ra * FST + 8 * s + lc + 4]);
            ap[s][3] = f2tf(Ps[rb * FST + 8 * s + lc + 4]);
        }
#pragma unroll
        for (int jn = 0; jn < 8; jn++) {
#pragma unroll
            for (int s = 0; s < 8; s++) {
                uint32_t bfr[2];
                bfr[0] = f2tf(Vs[(8 * s + lc) * FST + jn * 8 + lr]);
                bfr[1] = f2tf(Vs[(8 * s + lc + 4) * FST + jn * 8 + lr]);
                mma_tf32(O[jn], ap[s], bfr);
            }
        }
        __syncwarp();
    }

    const float ia = 1.f / l_a, ib = 1.f / l_b;
    float* o0 = out + ((size_t)(b * SEQ + q0 + qb + lr)) * HIDD + h * DH;
    float* o1 = o0 + (size_t)8 * HIDD;
#pragma unroll
    for (int jn = 0; jn < 8; jn++) {
        *(float2*)(o0 + jn * 8 + 2 * lc) = make_float2(O[jn][0] * ia, O[jn][1] * ia);
        *(float2*)(o1 + jn * 8 + 2 * lc) = make_float2(O[jn][2] * ib, O[jn][3] * ib);
    }
}

// ---------------- small kernels ----------------
__global__ void zero_f(float* __restrict__ p, int n) {
    int i = blockIdx.x * 256 + threadIdx.x;
    if (i < n) p[i] = 0.f;
}

__global__ void pack_w(const float* __restrict__ wq, const float* __restrict__ wkc,
                       const float* __restrict__ wv, float* __restrict__ W)
{
    int i = blockIdx.x * 256 + threadIdx.x;
    int r = i >> 10, c = i & 1023;
    float* dst = W + (size_t)r * H3 + c;
    dst[0]    = wq[i];
    dst[1024] = wkc[i];
    dst[2048] = wv[i];
}

__global__ void add_bias2(const float* __restrict__ src, int ld,
                          const float* __restrict__ cb, const float* __restrict__ pb,
                          float* __restrict__ ocb, float* __restrict__ opb)
{
    const int row = blockIdx.x, t = threadIdx.x;
    const float* s = src + (size_t)row * ld;
    float* o1 = ocb + (size_t)row * HIDD;
    float* o2 = opb + (size_t)row * HIDD;
    for (int i = t; i < HIDD; i += 256) {
        float v = s[i];
        o1[i] = v + cb[i];
        o2[i] = v + pb[i];
    }
}

__global__ void scatter_q(const float* __restrict__ tmap, const float* __restrict__ qg,
                          float* __restrict__ qscat, int* __restrict__ idx)
{
    const int b = blockIdx.y, p = blockIdx.x, t = threadIdx.x;
    __shared__ int sidx;
    const float* row = tmap + ((size_t)b * PQ + p) * SEQ;
    for (int s = t; s < SEQ; s += 128)
        if (row[s] > 0.5f) sidx = s;
    __syncthreads();
    const int si = sidx;
    if (t == 0) idx[b * PQ + p] = si;
    const float* src = qg + ((size_t)b * PQ + p) * HIDD;
    float* dst = qscat + ((size_t)b * SEQ + si) * HIDD;
    for (int i = t; i < HIDD; i += 128) atomicAdd(&dst[i], src[i]);
}

__global__ void gather_q(const float* __restrict__ qscat, const int* __restrict__ idx,
                         float* __restrict__ qq)
{
    const int b = blockIdx.y, p = blockIdx.x, t = threadIdx.x;
    const int si = idx[b * PQ + p];
    const float* src = qscat + ((size_t)b * SEQ + si) * HIDD;
    float* dst = qq + ((size_t)b * PQ + p) * HIDD;
    for (int i = t; i < HIDD; i += 128) dst[i] = src[i];
}

// ---------------- query-stream softmax (unchanged) ----------------
__global__ __launch_bounds__(256) void softmax_kernel(
    float* __restrict__ cs, const float* __restrict__ pp,
    const float* __restrict__ qArr, const float* __restrict__ sb,
    const float* __restrict__ seg, const void* __restrict__ segmat,
    const float* __restrict__ mask, const int* __restrict__ qidx,
    int Mrows, long qBatchStride, int ldq)
{
    const int b = blockIdx.z, h = blockIdx.y, qo = blockIdx.x, t = threadIdx.x;
    const int qrow = qidx ? qidx[b * PQ + qo] : qo;
    const int z = b * NH + h;
    const int mode = g_segmode[0];

    float* csrow = cs + ((size_t)z * Mrows + qo) * SEQ;
    const float* pprow = pp + ((size_t)z * Mrows + qo) * SEQ2 + (SEQ - qrow);
    const float* mrow = mask + ((size_t)b * SEQ + qrow) * SEQ;
    const size_t segbase = ((size_t)b * SEQ + qrow) * SEQ;

    __shared__ float qsv[DH];
    __shared__ float s01[2];
    __shared__ float red[256];

    if (t < DH)
        qsv[t] = qArr[qBatchStride * b + (size_t)qo * ldq + h * DH + t] + sb[h * DH + t];
    __syncthreads();
    if (t < 64) {
        const int which = t >> 5, lx = t & 31;
        const float* sgp = seg + which * NH * DH + h * DH;
        float a = qsv[lx] * sgp[lx] + qsv[lx + 32] * sgp[lx + 32];
#pragma unroll
        for (int o = 16; o; o >>= 1) a += __shfl_xor_sync(0xffffffffu, a, o);
        if (lx == 0) s01[which] = a;
    }
    __syncthreads();
    const float s0 = s01[0], s1 = s01[1];

    float lg[4];
    float mx = -3.4e38f;
#pragma unroll
    for (int j = 0; j < 4; j++) {
        int k = t + j * 256;
        float sgv = seg_at(segmat, segbase + k, mode) ? s1 : s0;
        float v = (csrow[k] + pprow[k] + sgv) * 0.125f + mrow[k] * (-1e9f);
        lg[j] = v;
        mx = fmaxf(mx, v);
    }
    red[t] = mx; __syncthreads();
#pragma unroll
    for (int s2 = 128; s2; s2 >>= 1) {
        if (t < s2) red[t] = fmaxf(red[t], red[t + s2]);
        __syncthreads();
    }
    mx = red[0]; __syncthreads();

    float sum = 0.f;
#pragma unroll
    for (int j = 0; j < 4; j++) {
        float e = __expf(lg[j] - mx);
        lg[j] = e;
        sum += e;
    }
    red[t] = sum; __syncthreads();
#pragma unroll
    for (int s2 = 128; s2; s2 >>= 1) {
        if (t < s2) red[t] += red[t + s2];
        __syncthreads();
    }
    const float invZ = 1.f / red[0];
#pragma unroll
    for (int j = 0; j < 4; j++) csrow[t + j * 256] = lg[j] * invZ;
}

// ---------------- launch ----------------
extern "C" void kernel_launch(void* const* d_in, const int* in_sizes, int n_in,
                              void* d_out, int out_size)
{
    const float* content = (const float*)d_in[0];
    const float* query   = (const float*)d_in[1];
    const float* pe      = (const float*)d_in[2];
    const void*  segmat  = d_in[3];
    const float* segenc  = (const float*)d_in[4];
    const float* segbias = (const float*)d_in[5];
    const float* cmask   = (const float*)d_in[6];
    const float* qmask   = (const float*)d_in[7];
    const float* tmap    = (const float*)d_in[8];
    const float* cbias   = (const float*)d_in[9];
    const float* pbias   = (const float*)d_in[10];
    const float* wq      = (const float*)d_in[11];
    const float* wkc     = (const float*)d_in[12];
    const float* wv      = (const float*)d_in[13];
    const float* wkp     = (const float*)d_in[14];
    const float* wo      = (const float*)d_in[15];
    float* out = (float*)d_out;

    float *qkv, *wpack, *kp, *qg, *qscat, *qq, *qqcb, *qqpb;
    float *csq, *ppq, *catt, *qatt;
    int* idx;
    cudaGetSymbolAddress((void**)&qkv,   g_qkv);
    cudaGetSymbolAddress((void**)&wpack, g_wpack);
    cudaGetSymbolAddress((void**)&kp,    g_kp);
    cudaGetSymbolAddress((void**)&qg,    g_qg);
    cudaGetSymbolAddress((void**)&qscat, g_qscat);
    cudaGetSymbolAddress((void**)&qq,    g_qq);
    cudaGetSymbolAddress((void**)&qqcb,  g_qqcb);
    cudaGetSymbolAddress((void**)&qqpb,  g_qqpb);
    cudaGetSymbolAddress((void**)&csq,   g_csq);
    cudaGetSymbolAddress((void**)&ppq,   g_ppq);
    cudaGetSymbolAddress((void**)&catt,  g_catt);
    cudaGetSymbolAddress((void**)&qatt,  g_qatt);
    cudaGetSymbolAddress((void**)&idx,   g_idx);

    static bool attr_done = false;
    if (!attr_done) {
        cudaFuncSetAttribute(flash_content, cudaFuncAttributeMaxDynamicSharedMemorySize,
                             (3 * 64 * FST + 4 * RT + 256) * 4);
        attr_done = true;
    }

    probe_segmat<<<1, 32>>>((const uint32_t*)segmat);
    zero_f<<<(BATCH * SEQ * HIDD + 255) / 256, 256>>>(qscat, BATCH * SEQ * HIDD);
    pack_w<<<4096, 256>>>(wq, wkc, wv, wpack);

    const long SH = (long)SEQ * HIDD, S2H = (long)SEQ2 * HIDD, PH = (long)PQ * HIDD;
    const long SH3 = (long)SEQ * H3;
    const long PS = (long)PQ * SEQ, PS2 = (long)PQ * SEQ2;

    // projections
    gemm_tf32<false><<<dim3(48, 16, 1), 256>>>(content, wpack, qkv,
        2048, H3, HIDD, HIDD, H3, H3, 0,0,0,0,0,0, 1);
    gemm_tf32<false><<<dim3(16, 32, 1), 256>>>(pe, wkp, kp,
        4096, HIDD, HIDD, HIDD, HIDD, HIDD, 0,0,0,0,0,0, 1);
    gemm_tf32<false><<<dim3(16, 2, 1), 256>>>(query, wq, qg,
        256, HIDD, HIDD, HIDD, HIDD, HIDD, 0,0,0,0,0,0, 1);

    scatter_q<<<dim3(PQ, BATCH), 128>>>(tmap, qg, qscat, idx);
    gather_q<<<dim3(PQ, BATCH), 128>>>(qscat, idx, qq);
    add_bias2<<<BATCH * PQ, 256>>>(qq, HIDD, cbias, pbias, qqcb, qqpb);

    const float* kcp = qkv + 1024;
    const float* vp  = qkv + 2048;

    // content stream: flash-fused
    flash_content<<<dim3(SEQ / 128, NH, BATCH), 256, (3 * 64 * FST + 4 * RT + 256) * 4>>>(
        qkv, kp, cbias, pbias, segbias, segenc, segmat, cmask, catt);

    // query stream: GEMM + softmax + AV path
    gemm_tf32<true><<<dim3(16, 1, BATCH * NH), 256>>>(qqcb, kcp, csq,
        PQ, SEQ, DH, HIDD, H3, SEQ,  PH, DH, SH3, DH, (long)NH * PS, PS, NH);
    gemm_tf32<true><<<dim3(32, 1, BATCH * NH), 256>>>(qqpb, kp, ppq,
        PQ, SEQ2, DH, HIDD, HIDD, SEQ2, PH, DH, S2H, DH, (long)NH * PS2, PS2, NH);
    softmax_kernel<<<dim3(PQ, NH, BATCH), 256>>>(
        csq, ppq, qq, segbias, segenc, segmat, qmask, idx, PQ, PH, HIDD);
    gemm_tf32<false><<<dim3(1, 1, BATCH * NH), 256>>>(csq, vp, qatt,
        PQ, DH, SEQ, SEQ, H3, HIDD, (long)NH * PS, PS, SH3, DH, PH, DH, NH);

    // output projections
    gemm_tf32<false><<<dim3(16, 16, 1), 256>>>(catt, wo, out,
        2048, HIDD, HIDD, HIDD, HIDD, HIDD, 0,0,0,0,0,0, 1);
    gemm_tf32<false><<<dim3(16, 2, 1), 256>>>(qatt, wo, out + (size_t)BATCH * SEQ * HIDD,
        256, HIDD, HIDD, HIDD, HIDD, HIDD, 0,0,0,0,0,0, 1);
}